// round 6
// baseline (speedup 1.0000x reference)
#include <cuda_runtime.h>
#include <math.h>

#define B_  2
#define S_  2048
#define D_  1024
#define H_  16
#define HD_ 64
#define EPS_ 1e-6f
// (1/sqrt(hd)) * log2(e), folded into q during fused rmsnorm
#define QFOLD 0.18033688011112042f

// Scratch (__device__ globals: allocation-free rule)
__device__ float g_qkv[B_ * S_ * 3 * D_];   // qkv, tf32-rounded values
__device__ float g_o  [B_ * S_ * D_];       // attention out, tf32-rounded
__device__ float g_xt [B_ * S_ * D_];       // x, tf32-rounded
__device__ float g_wq [3 * D_ * D_];        // Wqkv^T [3D][D], tf32-rounded
__device__ float g_wo [D_ * D_];            // Wout^T [D][D],  tf32-rounded

// ---------------------------------------------------------------------------
__device__ __forceinline__ unsigned f2tf(float x) {
    unsigned r;
    asm("cvt.rna.tf32.f32 %0, %1;" : "=r"(r) : "f"(x));
    return r;
}
__device__ __forceinline__ float tfr(float x) { return __uint_as_float(f2tf(x)); }

__device__ __forceinline__ void mma_tf32(float* c, const unsigned* a, const unsigned* b) {
    asm volatile(
        "mma.sync.aligned.m16n8k8.row.col.f32.tf32.tf32.f32 "
        "{%0,%1,%2,%3}, {%4,%5,%6,%7}, {%8,%9}, {%0,%1,%2,%3};"
        : "+f"(c[0]), "+f"(c[1]), "+f"(c[2]), "+f"(c[3])
        : "r"(a[0]), "r"(a[1]), "r"(a[2]), "r"(a[3]), "r"(b[0]), "r"(b[1]));
}
__device__ __forceinline__ void ldsm4(unsigned& r0, unsigned& r1, unsigned& r2,
                                      unsigned& r3, unsigned addr) {
    asm volatile("ldmatrix.sync.aligned.m8n8.x4.shared.b16 {%0,%1,%2,%3}, [%4];"
        : "=r"(r0), "=r"(r1), "=r"(r2), "=r"(r3) : "r"(addr));
}
__device__ __forceinline__ unsigned sptr(const void* p) {
    return (unsigned)__cvta_generic_to_shared(p);
}
__device__ __forceinline__ void cpa16(unsigned dst, const void* src) {
    asm volatile("cp.async.cg.shared.global [%0], [%1], 16;" :: "r"(dst), "l"(src));
}
__device__ __forceinline__ void cpa4(unsigned dst, const void* src) {
    asm volatile("cp.async.ca.shared.global [%0], [%1], 4;" :: "r"(dst), "l"(src));
}
__device__ __forceinline__ void cp_commit() {
    asm volatile("cp.async.commit_group;");
}
template<int Np>
__device__ __forceinline__ void cp_wait() {
    asm volatile("cp.async.wait_group %0;" :: "n"(Np));
}

// ---------------------------------------------------------------------------
// tf32-round a contiguous array (float4 granular)
__global__ void cvt_kernel(const float* __restrict__ in, float* __restrict__ out, int n4) {
    int i = blockIdx.x * blockDim.x + threadIdx.x;
    if (i < n4) {
        float4 v = ((const float4*)in)[i];
        ((uint4*)out)[i] = make_uint4(f2tf(v.x), f2tf(v.y), f2tf(v.z), f2tf(v.w));
    }
}

// tf32-round + transpose: in[K][N] -> out[N][K]
__global__ __launch_bounds__(256) void tcvt_kernel(
    const float* __restrict__ in, float* __restrict__ out, int K, int N)
{
    __shared__ float t[32][33];
    int n0 = blockIdx.x * 32, k0 = blockIdx.y * 32;
    int tx = threadIdx.x & 31, ty = threadIdx.x >> 5;
#pragma unroll
    for (int r = ty; r < 32; r += 8)
        t[r][tx] = in[(size_t)(k0 + r) * N + n0 + tx];
    __syncthreads();
#pragma unroll
    for (int r = ty; r < 32; r += 8)
        out[(size_t)(n0 + r) * K + k0 + tx] = tfr(t[tx][r]);
}

// ---------------------------------------------------------------------------
// TF32 GEMM + bias (+fused per-head RMSNorm when MODE==1).
// C[M,N] = A[M,K] @ Bt^T + bias ; Bt is [N][K] (pre-transposed, pre-rounded).
// 128x128x32 tile, 8 warps, warp 32x64. cp.async double-buffered.
// ---------------------------------------------------------------------------
#define GST 36
#define G_STAGE (128 * GST * 4)   // bytes per stage per operand

template<int N, int K, int MODE>
__global__ __launch_bounds__(256, 2) void gemm_tf32(
    const float* __restrict__ A, const float* __restrict__ Bt,
    const float* __restrict__ bias, float* __restrict__ C,
    const float* __restrict__ q_scale, const float* __restrict__ k_scale)
{
    extern __shared__ float smem[];
    float* As = smem;                    // 2 stages x 128*GST
    float* Bs = smem + 2 * 128 * GST;    // 2 stages x 128*GST

    const int tid = threadIdx.x;
    const int lane = tid & 31;
    const int wid = tid >> 5;
    const int g = lane >> 2;
    const int q = lane & 3;
    const int wm = wid >> 1;
    const int wn = wid & 1;
    const int bxn = blockIdx.x * 128;
    const int bym = blockIdx.y * 128;

    // copy mapping: idx -> (row 0..127, 16B-chunk 0..7); both operands [row][k]
    const float* asrc[4]; const float* bsrc[4];
    unsigned adst[4], bdst[4];
#pragma unroll
    for (int i = 0; i < 4; ++i) {
        int idx = tid + 256 * i, r = idx >> 3, c = idx & 7;
        asrc[i] = A  + (size_t)(bym + r) * K + c * 4;
        bsrc[i] = Bt + (size_t)(bxn + r) * K + c * 4;
        adst[i] = sptr(As) + (r * GST + c * 4) * 4;
        bdst[i] = sptr(Bs) + (r * GST + c * 4) * 4;
    }

    const unsigned a_base = sptr(As) + (((wm * 32 + (lane & 15)) * GST + (lane >> 4) * 4) << 2);
    const unsigned b_base = sptr(Bs) + ((((wn * 64 + (lane & 7) + ((lane >> 4) << 3))) * GST
                                         + ((lane >> 3) & 1) * 4) << 2);

    float acc[2][8][4];
#pragma unroll
    for (int mf = 0; mf < 2; ++mf)
#pragma unroll
        for (int nf = 0; nf < 8; ++nf)
#pragma unroll
            for (int e = 0; e < 4; ++e) acc[mf][nf][e] = 0.f;

    // prologue: tile 0 -> stage 0
#pragma unroll
    for (int i = 0; i < 4; ++i) { cpa16(adst[i], asrc[i]); cpa16(bdst[i], bsrc[i]); }
    cp_commit();

    const int KT = K / 32;
    int koff = 0;
    for (int kt = 0; kt < KT; ++kt) {
        if (kt + 1 < KT) {
            koff += 32;
            unsigned so = ((kt + 1) & 1) * G_STAGE;
#pragma unroll
            for (int i = 0; i < 4; ++i) {
                cpa16(adst[i] + so, asrc[i] + koff);
                cpa16(bdst[i] + so, bsrc[i] + koff);
            }
            cp_commit();
            cp_wait<1>();
        } else {
            cp_wait<0>();
        }
        __syncthreads();

        const unsigned a_s = a_base + (kt & 1) * G_STAGE;
        const unsigned b_s = b_base + (kt & 1) * G_STAGE;
#pragma unroll
        for (int kk = 0; kk < 4; ++kk) {
            unsigned a0[4], a1[4], bl[4][4];
            ldsm4(a0[0], a0[1], a0[2], a0[3], a_s + kk * 32);
            ldsm4(a1[0], a1[1], a1[2], a1[3], a_s + 16 * GST * 4 + kk * 32);
#pragma unroll
            for (int t2 = 0; t2 < 4; ++t2)
                ldsm4(bl[t2][0], bl[t2][1], bl[t2][2], bl[t2][3],
                      b_s + t2 * 16 * GST * 4 + kk * 32);
#pragma unroll
            for (int nf = 0; nf < 8; ++nf) {
                const unsigned* bf = &bl[nf >> 1][(nf & 1) * 2];
                mma_tf32(acc[0][nf], a0, bf);
                mma_tf32(acc[1][nf], a1, bf);
            }
        }
        __syncthreads();   // stage reusable
    }

    // epilogue: bias (+fused rmsnorm), MODE==1 -> store tf32-rounded
    const bool donorm = (MODE == 1) && (bxn < 2048);
    const float* sc = (bxn < 1024) ? q_scale : k_scale;
    const float fold = (bxn < 1024) ? QFOLD : 1.0f;

#pragma unroll
    for (int mf = 0; mf < 2; ++mf) {
        int r0 = bym + wm * 32 + mf * 16 + g;
#pragma unroll
        for (int nf = 0; nf < 8; ++nf) {
            int col = bxn + wn * 64 + nf * 8 + 2 * q;
            float2 bs = *(const float2*)(bias + col);
            acc[mf][nf][0] += bs.x; acc[mf][nf][1] += bs.y;
            acc[mf][nf][2] += bs.x; acc[mf][nf][3] += bs.y;
        }
        if (donorm) {
#pragma unroll
            for (int rh = 0; rh < 2; ++rh) {
                const int e0 = rh * 2, e1 = e0 + 1;
                float ss = 0.f;
#pragma unroll
                for (int nf = 0; nf < 8; ++nf)
                    ss += acc[mf][nf][e0] * acc[mf][nf][e0]
                        + acc[mf][nf][e1] * acc[mf][nf][e1];
                ss += __shfl_xor_sync(0xffffffffu, ss, 1);
                ss += __shfl_xor_sync(0xffffffffu, ss, 2);
                float rr = rsqrtf(ss * (1.0f / HD_) + EPS_) * fold;
#pragma unroll
                for (int nf = 0; nf < 8; ++nf) {
                    float2 s2 = *(const float2*)(sc + nf * 8 + 2 * q);
                    acc[mf][nf][e0] *= rr * s2.x;
                    acc[mf][nf][e1] *= rr * s2.y;
                }
            }
        }
#pragma unroll
        for (int nf = 0; nf < 8; ++nf) {
            int col = bxn + wn * 64 + nf * 8 + 2 * q;
            float v0 = acc[mf][nf][0], v1 = acc[mf][nf][1];
            float v2 = acc[mf][nf][2], v3 = acc[mf][nf][3];
            if (MODE == 1) { v0 = tfr(v0); v1 = tfr(v1); v2 = tfr(v2); v3 = tfr(v3); }
            *(float2*)(C + (size_t)r0 * N + col) = make_float2(v0, v1);
            *(float2*)(C + (size_t)(r0 + 8) * N + col) = make_float2(v2, v3);
        }
    }
}

// ---------------------------------------------------------------------------
// TF32 flash attention, cp.async double-buffered K/V, full LDSM.
// CTA: 256 thr (8 warps), 128 queries, warp = 16 q-rows x 64 keys.
// qkv values are already tf32-rounded by the QKV GEMM epilogue.
// ---------------------------------------------------------------------------
#define TS 68
#define KV_STAGE (64 * TS * 4)     // bytes per stage
#define OFF_K  (128 * TS)
#define OFF_V  (OFF_K + 2 * 64 * TS)
#define OFF_P  (OFF_V + 2 * 64 * TS)
#define ATT_SMEM ((OFF_P + 128 * TS) * 4)

__global__ __launch_bounds__(256) void attn_tf32(
    const float* __restrict__ qkv, float* __restrict__ o)
{
    extern __shared__ float smem[];
    float* Qs = smem;
    float* Ks = smem + OFF_K;
    float* Vt = smem + OFF_V;
    float* Ps = smem + OFF_P;

    const int tid = threadIdx.x;
    const int lane = tid & 31;
    const int w = tid >> 5;
    const int g = lane >> 2;
    const int q = lane & 3;
    const int q0 = blockIdx.x * 128;
    const int bh = blockIdx.y;
    const int b = bh >> 4;
    const int h = bh & 15;

    const float* base = qkv + (size_t)b * S_ * 3 * D_ + h * HD_;

    // K copy mapping: 4 x 16B chunks (64 rows x 16 chunks)
    const float* ksrc[4];
    unsigned kdst[4];
#pragma unroll
    for (int i = 0; i < 4; ++i) {
        int idx = tid + 256 * i, r = idx >> 4, c = idx & 15;
        ksrc[i] = base + (size_t)r * (3 * D_) + D_ + c * 4;
        kdst[i] = sptr(Ks) + (r * TS + c * 4) * 4;
    }
    // V copy mapping: one hd column, 16 keys, 4B copies (transpose on store)
    const int vhd = (tid & 31) + ((tid >> 5) & 1) * 32;
    const int vk0 = (tid >> 6) * 16;
    const float* vsrc = base + (size_t)vk0 * (3 * D_) + 2 * D_ + vhd;
    const unsigned vdst = sptr(Vt) + (vhd * TS + vk0) * 4;

    // prologue: Q (full 128x64 tile = 2048 16B-chunks) + KV tile 0, one group
#pragma unroll
    for (int i = 0; i < 8; ++i) {
        int idx = tid + 256 * i, r = idx >> 4, c = idx & 15;
        cpa16(sptr(Qs) + (r * TS + c * 4) * 4,
              base + (size_t)(q0 + r) * (3 * D_) + c * 4);
    }
#pragma unroll
    for (int i = 0; i < 4; ++i) cpa16(kdst[i], ksrc[i]);
#pragma unroll
    for (int j = 0; j < 16; ++j) cpa4(vdst + j * 4, vsrc + (size_t)j * (3 * D_));
    cp_commit();

    const unsigned qbase = sptr(Qs) + (((w * 16 + (lane & 15)) * TS + (lane >> 4) * 4) << 2);
    const unsigned pbase = sptr(Ps) + (((w * 16 + (lane & 15)) * TS + (lane >> 4) * 4) << 2);
    const unsigned brow = (((lane & 7) + ((lane >> 4) << 3)) * TS + ((lane >> 3) & 1) * 4) << 2;
    const unsigned kbase = sptr(Ks) + brow;
    const unsigned vbase = sptr(Vt) + brow;

    float mst[2] = {-1e30f, -1e30f}, lst[2] = {0.f, 0.f};
    float acco[8][4];
#pragma unroll
    for (int nf = 0; nf < 8; ++nf)
#pragma unroll
        for (int e = 0; e < 4; ++e) acco[nf][e] = 0.f;

    const int T = S_ / 64;
    for (int t = 0; t < T; ++t) {
        if (t + 1 < T) {
            const int ko = (t + 1) * 64 * (3 * D_);
            const unsigned so = ((t + 1) & 1) * KV_STAGE;
#pragma unroll
            for (int i = 0; i < 4; ++i) cpa16(kdst[i] + so, ksrc[i] + ko);
#pragma unroll
            for (int j = 0; j < 16; ++j)
                cpa4(vdst + so + j * 4, vsrc + ko + (size_t)j * (3 * D_));
            cp_commit();
            cp_wait<1>();
        } else {
            cp_wait<0>();
        }
        __syncthreads();

        const unsigned k_s = kbase + (t & 1) * KV_STAGE;
        const unsigned v_s = vbase + (t & 1) * KV_STAGE;

        // S = Q K^T
        float accs[8][4];
#pragma unroll
        for (int nf = 0; nf < 8; ++nf)
#pragma unroll
            for (int e = 0; e < 4; ++e) accs[nf][e] = 0.f;
#pragma unroll
        for (int ks = 0; ks < 8; ++ks) {
            unsigned a[4], bl[4][4];
            ldsm4(a[0], a[1], a[2], a[3], qbase + ks * 32);
#pragma unroll
            for (int t2 = 0; t2 < 4; ++t2)
                ldsm4(bl[t2][0], bl[t2][1], bl[t2][2], bl[t2][3],
                      k_s + t2 * 16 * TS * 4 + ks * 32);
#pragma unroll
            for (int nf = 0; nf < 8; ++nf)
                mma_tf32(accs[nf], a, &bl[nf >> 1][(nf & 1) * 2]);
        }

        // online softmax (rows in quads)
#pragma unroll
        for (int rh = 0; rh < 2; ++rh) {
            const int e0 = rh * 2, e1 = e0 + 1;
            float mold = mst[rh];
            float mx = mold;
#pragma unroll
            for (int nf = 0; nf < 8; ++nf)
                mx = fmaxf(mx, fmaxf(accs[nf][e0], accs[nf][e1]));
            mx = fmaxf(mx, __shfl_xor_sync(0xffffffffu, mx, 1));
            mx = fmaxf(mx, __shfl_xor_sync(0xffffffffu, mx, 2));
            float corr = exp2f(mold - mx);
            mst[rh] = mx;
            float sum = 0.f;
            int rowb = (w * 16 + g + rh * 8) * TS + 2 * q;
#pragma unroll
            for (int nf = 0; nf < 8; ++nf) {
                float p0 = exp2f(accs[nf][e0] - mx);
                float p1 = exp2f(accs[nf][e1] - mx);
                sum += p0 + p1;
                *(uint2*)&Ps[rowb + nf * 8] = make_uint2(f2tf(p0), f2tf(p1));
                acco[nf][e0] *= corr;
                acco[nf][e1] *= corr;
            }
            sum += __shfl_xor_sync(0xffffffffu, sum, 1);
            sum += __shfl_xor_sync(0xffffffffu, sum, 2);
            lst[rh] = lst[rh] * corr + sum;
        }
        __syncwarp();   // P is warp-private

        // O += P V
#pragma unroll
        for (int ks = 0; ks < 8; ++ks) {
            unsigned a[4], bl[4][4];
            ldsm4(a[0], a[1], a[2], a[3], pbase + ks * 32);
#pragma unroll
            for (int t2 = 0; t2 < 4; ++t2)
                ldsm4(bl[t2][0], bl[t2][1], bl[t2][2], bl[t2][3],
                      v_s + t2 * 16 * TS * 4 + ks * 32);
#pragma unroll
            for (int nf = 0; nf < 8; ++nf)
                mma_tf32(acco[nf], a, &bl[nf >> 1][(nf & 1) * 2]);
        }
        __syncthreads();   // stage reusable for next issue
    }

    // epilogue: normalize, round to tf32 (out-proj consumes it), store
#pragma unroll
    for (int rh = 0; rh < 2; ++rh) {
        float inv = 1.0f / lst[rh];
        int row = q0 + w * 16 + g + rh * 8;
        float* orow = o + (size_t)(b * S_ + row) * D_ + h * HD_;
        const int e0 = rh * 2, e1 = e0 + 1;
#pragma unroll
        for (int nf = 0; nf < 8; ++nf)
            *(float2*)(orow + nf * 8 + 2 * q) =
                make_float2(tfr(acco[nf][e0] * inv), tfr(acco[nf][e1] * inv));
    }
}

// ---------------------------------------------------------------------------
extern "C" void kernel_launch(void* const* d_in, const int* in_sizes, int n_in,
                              void* d_out, int out_size)
{
    const float* x       = (const float*)d_in[0];
    const float* Wqkv    = (const float*)d_in[1];
    const float* bqkv    = (const float*)d_in[2];
    const float* Wout    = (const float*)d_in[3];
    const float* bout    = (const float*)d_in[4];
    const float* q_scale = (const float*)d_in[5];
    const float* k_scale = (const float*)d_in[6];
    float* out = (float*)d_out;

    float* qkv; cudaGetSymbolAddress((void**)&qkv, g_qkv);
    float* o;   cudaGetSymbolAddress((void**)&o,   g_o);
    float* xt;  cudaGetSymbolAddress((void**)&xt,  g_xt);
    float* wq;  cudaGetSymbolAddress((void**)&wq,  g_wq);
    float* wo;  cudaGetSymbolAddress((void**)&wo,  g_wo);

    const int GEMM_SMEM = 4 * 128 * GST * 4;
    cudaFuncSetAttribute((const void*)gemm_tf32<3 * D_, D_, 1>,
                         cudaFuncAttributeMaxDynamicSharedMemorySize, GEMM_SMEM);
    cudaFuncSetAttribute((const void*)gemm_tf32<D_, D_, 0>,
                         cudaFuncAttributeMaxDynamicSharedMemorySize, GEMM_SMEM);
    cudaFuncSetAttribute((const void*)attn_tf32,
                         cudaFuncAttributeMaxDynamicSharedMemorySize, ATT_SMEM);

    // 0) pre-round x, pre-round+transpose weights
    cvt_kernel<<<(B_ * S_ * D_ / 4 + 255) / 256, 256>>>(x, xt, B_ * S_ * D_ / 4);
    tcvt_kernel<<<dim3(3 * D_ / 32, D_ / 32), 256>>>(Wqkv, wq, D_, 3 * D_);
    tcvt_kernel<<<dim3(D_ / 32, D_ / 32), 256>>>(Wout, wo, D_, D_);

    // 1) QKV projection + fused RMSNorm (outputs tf32-rounded)
    gemm_tf32<3 * D_, D_, 1><<<dim3(3 * D_ / 128, (B_ * S_) / 128), 256, GEMM_SMEM>>>(
        xt, wq, bqkv, qkv, q_scale, k_scale);

    // 2) attention
    attn_tf32<<<dim3(S_ / 128, B_ * H_), 256, ATT_SMEM>>>(qkv, o);

    // 3) output projection (fp32 output, no rounding)
    gemm_tf32<D_, D_, 0><<<dim3(D_ / 128, (B_ * S_) / 128), 256, GEMM_SMEM>>>(
        o, wo, bout, out, q_scale, k_scale);
}

// round 7
// speedup vs baseline: 1.5170x; 1.5170x over previous
#include <cuda_runtime.h>
#include <cuda_fp16.h>
#include <math.h>

#define B_  2
#define S_  2048
#define D_  1024
#define H_  16
#define HD_ 64
#define EPS_ 1e-6f
// (1/sqrt(hd)) * log2(e), folded into q during fused rmsnorm
#define QFOLD 0.18033688011112042f

// Scratch (__device__ globals: allocation-free rule)
__device__ __half g_qkvh[B_ * S_ * 3 * D_];  // qkv in fp16 (post-norm q,k)
__device__ float  g_o [B_ * S_ * D_];        // attention out, tf32-rounded
__device__ float  g_xt[B_ * S_ * D_];        // x, tf32-rounded
__device__ float  g_wq[3 * D_ * D_];         // Wqkv^T [3D][D], tf32-rounded
__device__ float  g_wo[D_ * D_];             // Wout^T [D][D],  tf32-rounded

// ---------------------------------------------------------------------------
__device__ __forceinline__ unsigned f2tf(float x) {
    unsigned r;
    asm("cvt.rna.tf32.f32 %0, %1;" : "=r"(r) : "f"(x));
    return r;
}
__device__ __forceinline__ float tfr(float x) { return __uint_as_float(f2tf(x)); }

__device__ __forceinline__ void mma_tf32(float* c, const unsigned* a, const unsigned* b) {
    asm volatile(
        "mma.sync.aligned.m16n8k8.row.col.f32.tf32.tf32.f32 "
        "{%0,%1,%2,%3}, {%4,%5,%6,%7}, {%8,%9}, {%0,%1,%2,%3};"
        : "+f"(c[0]), "+f"(c[1]), "+f"(c[2]), "+f"(c[3])
        : "r"(a[0]), "r"(a[1]), "r"(a[2]), "r"(a[3]), "r"(b[0]), "r"(b[1]));
}
__device__ __forceinline__ void mma_f16(float* c, const unsigned* a, const unsigned* b) {
    asm volatile(
        "mma.sync.aligned.m16n8k16.row.col.f32.f16.f16.f32 "
        "{%0,%1,%2,%3}, {%4,%5,%6,%7}, {%8,%9}, {%0,%1,%2,%3};"
        : "+f"(c[0]), "+f"(c[1]), "+f"(c[2]), "+f"(c[3])
        : "r"(a[0]), "r"(a[1]), "r"(a[2]), "r"(a[3]), "r"(b[0]), "r"(b[1]));
}
__device__ __forceinline__ void ldsm4(unsigned& r0, unsigned& r1, unsigned& r2,
                                      unsigned& r3, unsigned addr) {
    asm volatile("ldmatrix.sync.aligned.m8n8.x4.shared.b16 {%0,%1,%2,%3}, [%4];"
        : "=r"(r0), "=r"(r1), "=r"(r2), "=r"(r3) : "r"(addr));
}
__device__ __forceinline__ void ldsm4t(unsigned& r0, unsigned& r1, unsigned& r2,
                                       unsigned& r3, unsigned addr) {
    asm volatile("ldmatrix.sync.aligned.m8n8.x4.trans.shared.b16 {%0,%1,%2,%3}, [%4];"
        : "=r"(r0), "=r"(r1), "=r"(r2), "=r"(r3) : "r"(addr));
}
__device__ __forceinline__ unsigned sptr(const void* p) {
    return (unsigned)__cvta_generic_to_shared(p);
}
__device__ __forceinline__ void cpa16(unsigned dst, const void* src) {
    asm volatile("cp.async.cg.shared.global [%0], [%1], 16;" :: "r"(dst), "l"(src));
}
__device__ __forceinline__ void cp_commit() {
    asm volatile("cp.async.commit_group;");
}
template<int Np>
__device__ __forceinline__ void cp_wait() {
    asm volatile("cp.async.wait_group %0;" :: "n"(Np));
}

// ---------------------------------------------------------------------------
// tf32-round a contiguous array (float4 granular)
__global__ void cvt_kernel(const float* __restrict__ in, float* __restrict__ out, int n4) {
    int i = blockIdx.x * blockDim.x + threadIdx.x;
    if (i < n4) {
        float4 v = ((const float4*)in)[i];
        ((uint4*)out)[i] = make_uint4(f2tf(v.x), f2tf(v.y), f2tf(v.z), f2tf(v.w));
    }
}

// tf32-round + transpose: in[K][N] -> out[N][K]
__global__ __launch_bounds__(256) void tcvt_kernel(
    const float* __restrict__ in, float* __restrict__ out, int K, int N)
{
    __shared__ float t[32][33];
    int n0 = blockIdx.x * 32, k0 = blockIdx.y * 32;
    int tx = threadIdx.x & 31, ty = threadIdx.x >> 5;
#pragma unroll
    for (int r = ty; r < 32; r += 8)
        t[r][tx] = in[(size_t)(k0 + r) * N + n0 + tx];
    __syncthreads();
#pragma unroll
    for (int r = ty; r < 32; r += 8)
        out[(size_t)(n0 + r) * K + k0 + tx] = tfr(t[tx][r]);
}

// ---------------------------------------------------------------------------
// TF32 GEMM + bias. MODE==1: fused per-head RMSNorm on q,k; output fp16.
// C[M,N] = A[M,K] @ Bt^T + bias ; Bt is [N][K] (pre-transposed, pre-rounded).
// 128x128x32 tile, 8 warps, warp 32x64. cp.async, 3-stage pipeline.
// ---------------------------------------------------------------------------
#define GST 36
#define G_STAGE (128 * GST * 4)   // bytes per stage per operand
#define GEMM_SMEM (6 * 128 * GST * 4)

template<int N, int K, int MODE>
__global__ __launch_bounds__(256, 2) void gemm_tf32(
    const float* __restrict__ A, const float* __restrict__ Bt,
    const float* __restrict__ bias, void* __restrict__ Cv,
    const float* __restrict__ q_scale, const float* __restrict__ k_scale)
{
    extern __shared__ float smem[];
    float* As = smem;                    // 3 stages x 128*GST
    float* Bs = smem + 3 * 128 * GST;    // 3 stages x 128*GST

    const int tid = threadIdx.x;
    const int lane = tid & 31;
    const int wid = tid >> 5;
    const int g = lane >> 2;
    const int q = lane & 3;
    const int wm = wid >> 1;
    const int wn = wid & 1;
    const int bxn = blockIdx.x * 128;
    const int bym = blockIdx.y * 128;

    // copy mapping: idx -> (row 0..127, 16B-chunk 0..7); both operands [row][k]
    const float* asrc[4]; const float* bsrc[4];
    unsigned adst[4], bdst[4];
#pragma unroll
    for (int i = 0; i < 4; ++i) {
        int idx = tid + 256 * i, r = idx >> 3, c = idx & 7;
        asrc[i] = A  + (size_t)(bym + r) * K + c * 4;
        bsrc[i] = Bt + (size_t)(bxn + r) * K + c * 4;
        adst[i] = sptr(As) + (r * GST + c * 4) * 4;
        bdst[i] = sptr(Bs) + (r * GST + c * 4) * 4;
    }

    const unsigned a_base = sptr(As) + (((wm * 32 + (lane & 15)) * GST + (lane >> 4) * 4) << 2);
    const unsigned b_base = sptr(Bs) + ((((wn * 64 + (lane & 7) + ((lane >> 4) << 3))) * GST
                                         + ((lane >> 3) & 1) * 4) << 2);

    float acc[2][8][4];
#pragma unroll
    for (int mf = 0; mf < 2; ++mf)
#pragma unroll
        for (int nf = 0; nf < 8; ++nf)
#pragma unroll
            for (int e = 0; e < 4; ++e) acc[mf][nf][e] = 0.f;

    const int KT = K / 32;

    // prologue: stages 0 and 1
#pragma unroll
    for (int i = 0; i < 4; ++i) { cpa16(adst[i], asrc[i]); cpa16(bdst[i], bsrc[i]); }
    cp_commit();
#pragma unroll
    for (int i = 0; i < 4; ++i) {
        cpa16(adst[i] + G_STAGE, asrc[i] + 32);
        cpa16(bdst[i] + G_STAGE, bsrc[i] + 32);
    }
    cp_commit();

    for (int kt = 0; kt < KT; ++kt) {
        if (kt + 2 < KT) {
            const int koff = (kt + 2) * 32;
            const unsigned so = ((kt + 2) % 3) * G_STAGE;
#pragma unroll
            for (int i = 0; i < 4; ++i) {
                cpa16(adst[i] + so, asrc[i] + koff);
                cpa16(bdst[i] + so, bsrc[i] + koff);
            }
            cp_commit();
            cp_wait<2>();
        } else if (kt + 2 == KT) {
            cp_wait<1>();
        } else {
            cp_wait<0>();
        }
        __syncthreads();

        const unsigned a_s = a_base + (kt % 3) * G_STAGE;
        const unsigned b_s = b_base + (kt % 3) * G_STAGE;
#pragma unroll
        for (int kk = 0; kk < 4; ++kk) {
            unsigned a0[4], a1[4], bl[4][4];
            ldsm4(a0[0], a0[1], a0[2], a0[3], a_s + kk * 32);
            ldsm4(a1[0], a1[1], a1[2], a1[3], a_s + 16 * GST * 4 + kk * 32);
#pragma unroll
            for (int t2 = 0; t2 < 4; ++t2)
                ldsm4(bl[t2][0], bl[t2][1], bl[t2][2], bl[t2][3],
                      b_s + t2 * 16 * GST * 4 + kk * 32);
#pragma unroll
            for (int nf = 0; nf < 8; ++nf) {
                const unsigned* bf = &bl[nf >> 1][(nf & 1) * 2];
                mma_tf32(acc[0][nf], a0, bf);
                mma_tf32(acc[1][nf], a1, bf);
            }
        }
        __syncthreads();   // stage reusable
    }

    // epilogue
    const bool donorm = (MODE == 1) && (bxn < 2048);
    const float* sc = (bxn < 1024) ? q_scale : k_scale;
    const float fold = (bxn < 1024) ? QFOLD : 1.0f;

#pragma unroll
    for (int mf = 0; mf < 2; ++mf) {
        int r0 = bym + wm * 32 + mf * 16 + g;
#pragma unroll
        for (int nf = 0; nf < 8; ++nf) {
            int col = bxn + wn * 64 + nf * 8 + 2 * q;
            float2 bs = *(const float2*)(bias + col);
            acc[mf][nf][0] += bs.x; acc[mf][nf][1] += bs.y;
            acc[mf][nf][2] += bs.x; acc[mf][nf][3] += bs.y;
        }
        if (donorm) {
#pragma unroll
            for (int rh = 0; rh < 2; ++rh) {
                const int e0 = rh * 2, e1 = e0 + 1;
                float ss = 0.f;
#pragma unroll
                for (int nf = 0; nf < 8; ++nf)
                    ss += acc[mf][nf][e0] * acc[mf][nf][e0]
                        + acc[mf][nf][e1] * acc[mf][nf][e1];
                ss += __shfl_xor_sync(0xffffffffu, ss, 1);
                ss += __shfl_xor_sync(0xffffffffu, ss, 2);
                float rr = rsqrtf(ss * (1.0f / HD_) + EPS_) * fold;
#pragma unroll
                for (int nf = 0; nf < 8; ++nf) {
                    float2 s2 = *(const float2*)(sc + nf * 8 + 2 * q);
                    acc[mf][nf][e0] *= rr * s2.x;
                    acc[mf][nf][e1] *= rr * s2.y;
                }
            }
        }
#pragma unroll
        for (int nf = 0; nf < 8; ++nf) {
            int col = bxn + wn * 64 + nf * 8 + 2 * q;
            if (MODE == 1) {
                __half* Ch = (__half*)Cv;
                *(__half2*)(Ch + (size_t)r0 * N + col) =
                    __floats2half2_rn(acc[mf][nf][0], acc[mf][nf][1]);
                *(__half2*)(Ch + (size_t)(r0 + 8) * N + col) =
                    __floats2half2_rn(acc[mf][nf][2], acc[mf][nf][3]);
            } else {
                float* Cf = (float*)Cv;
                *(float2*)(Cf + (size_t)r0 * N + col) =
                    make_float2(acc[mf][nf][0], acc[mf][nf][1]);
                *(float2*)(Cf + (size_t)(r0 + 8) * N + col) =
                    make_float2(acc[mf][nf][2], acc[mf][nf][3]);
            }
        }
    }
}

// ---------------------------------------------------------------------------
// FP16 flash attention (fp32 accumulate). CTA: 256 thr (8 warps), 128 queries,
// warp = 16 q-rows x 64 keys. K,V stored [key][hd]; V B-frags via ldmatrix.trans.
// cp.async double-buffered K/V. Smem 73.7KB -> 2 CTAs/SM.
// ---------------------------------------------------------------------------
#define HTS 72                       // halves per row (144B, conflict-free)
#define OFK (128 * HTS)
#define OFV (OFK + 2 * 64 * HTS)
#define OFP (OFV + 2 * 64 * HTS)
#define KVSTG (64 * HTS * 2)         // bytes per K (or V) stage
#define ATT_SMEM ((OFP + 128 * HTS) * 2)

__global__ __launch_bounds__(256, 2) void attn_f16(
    const __half* __restrict__ qkv, float* __restrict__ o)
{
    extern __shared__ __half smh[];
    __half* Qh = smh;
    __half* Kh = smh + OFK;
    __half* Vh = smh + OFV;
    __half* Ph = smh + OFP;

    const int tid = threadIdx.x;
    const int lane = tid & 31;
    const int w = tid >> 5;
    const int g = lane >> 2;
    const int q = lane & 3;
    const int q0 = blockIdx.x * 128;
    const int bh = blockIdx.y;
    const int b = bh >> 4;
    const int h = bh & 15;

    const __half* base = qkv + (size_t)b * S_ * 3 * D_ + h * HD_;

    // K/V copy mapping: 2 x 16B chunks each (64 rows x 8 chunks)
    const __half* ksrc[2]; const __half* vsrc[2];
    unsigned kdst[2], vdst[2];
#pragma unroll
    for (int i = 0; i < 2; ++i) {
        int idx = tid + 256 * i, r = idx >> 3, c = idx & 7;
        ksrc[i] = base + (size_t)r * (3 * D_) + D_ + c * 8;
        vsrc[i] = base + (size_t)r * (3 * D_) + 2 * D_ + c * 8;
        kdst[i] = sptr(Kh) + (r * HTS + c * 8) * 2;
        vdst[i] = sptr(Vh) + (r * HTS + c * 8) * 2;
    }

    // prologue: Q (128 rows x 8 chunks) + K/V tile 0, one commit group
#pragma unroll
    for (int i = 0; i < 4; ++i) {
        int idx = tid + 256 * i, r = idx >> 3, c = idx & 7;
        cpa16(sptr(Qh) + (r * HTS + c * 8) * 2,
              base + (size_t)(q0 + r) * (3 * D_) + c * 8);
    }
#pragma unroll
    for (int i = 0; i < 2; ++i) { cpa16(kdst[i], ksrc[i]); cpa16(vdst[i], vsrc[i]); }
    cp_commit();

    // ldmatrix bases (bytes)
    const unsigned arow = ((w * 16 + (lane & 15)) * HTS) * 2 + (lane >> 4) * 16;
    const unsigned qbase = sptr(Qh) + arow;
    const unsigned pbase = sptr(Ph) + arow;
    const unsigned kbase = sptr(Kh)
        + (((lane & 7) + ((lane >> 4) << 3)) * HTS) * 2 + ((lane >> 3) & 1) * 16;
    const unsigned vbase = sptr(Vh)
        + (((lane & 7) + (((lane >> 3) & 1) << 3)) * HTS) * 2 + (lane >> 4) * 16;

    float mst[2] = {-1e30f, -1e30f}, lst[2] = {0.f, 0.f};
    float acco[8][4];
#pragma unroll
    for (int nf = 0; nf < 8; ++nf)
#pragma unroll
        for (int e = 0; e < 4; ++e) acco[nf][e] = 0.f;

    const int T = S_ / 64;
    for (int t = 0; t < T; ++t) {
        if (t + 1 < T) {
            const size_t ko = (size_t)(t + 1) * 64 * (3 * D_);
            const unsigned so = ((t + 1) & 1) * KVSTG;
#pragma unroll
            for (int i = 0; i < 2; ++i) {
                cpa16(kdst[i] + so, ksrc[i] + ko);
                cpa16(vdst[i] + so, vsrc[i] + ko);
            }
            cp_commit();
            cp_wait<1>();
        } else {
            cp_wait<0>();
        }
        __syncthreads();

        const unsigned k_s = kbase + (t & 1) * KVSTG;
        const unsigned v_s = vbase + (t & 1) * KVSTG;

        // S = Q K^T  (hd=64 -> 4 k16 iters; 64 keys -> 8 n-frags)
        float accs[8][4];
#pragma unroll
        for (int nf = 0; nf < 8; ++nf)
#pragma unroll
            for (int e = 0; e < 4; ++e) accs[nf][e] = 0.f;
#pragma unroll
        for (int ks = 0; ks < 4; ++ks) {
            unsigned a[4], bl[4][4];
            ldsm4(a[0], a[1], a[2], a[3], qbase + ks * 32);
#pragma unroll
            for (int t2 = 0; t2 < 4; ++t2)
                ldsm4(bl[t2][0], bl[t2][1], bl[t2][2], bl[t2][3],
                      k_s + t2 * 16 * HTS * 2 + ks * 32);
#pragma unroll
            for (int nf = 0; nf < 8; ++nf)
                mma_f16(accs[nf], a, &bl[nf >> 1][(nf & 1) * 2]);
        }

        // online softmax (rows in quads)
#pragma unroll
        for (int rh = 0; rh < 2; ++rh) {
            const int e0 = rh * 2, e1 = e0 + 1;
            float mold = mst[rh];
            float mx = mold;
#pragma unroll
            for (int nf = 0; nf < 8; ++nf)
                mx = fmaxf(mx, fmaxf(accs[nf][e0], accs[nf][e1]));
            mx = fmaxf(mx, __shfl_xor_sync(0xffffffffu, mx, 1));
            mx = fmaxf(mx, __shfl_xor_sync(0xffffffffu, mx, 2));
            float corr = exp2f(mold - mx);
            mst[rh] = mx;
            float sum = 0.f;
            int rowb = (w * 16 + g + rh * 8) * HTS + 2 * q;
#pragma unroll
            for (int nf = 0; nf < 8; ++nf) {
                float p0 = exp2f(accs[nf][e0] - mx);
                float p1 = exp2f(accs[nf][e1] - mx);
                sum += p0 + p1;
                *(__half2*)(Ph + rowb + nf * 8) = __floats2half2_rn(p0, p1);
                acco[nf][e0] *= corr;
                acco[nf][e1] *= corr;
            }
            sum += __shfl_xor_sync(0xffffffffu, sum, 1);
            sum += __shfl_xor_sync(0xffffffffu, sum, 2);
            lst[rh] = lst[rh] * corr + sum;
        }
        __syncwarp();   // P is warp-private

        // O += P V  (keys 64 -> 4 k16 iters; hd 64 -> 8 n-frags; V via trans)
#pragma unroll
        for (int ks = 0; ks < 4; ++ks) {
            unsigned a[4], bl[4][4];
            ldsm4(a[0], a[1], a[2], a[3], pbase + ks * 32);
#pragma unroll
            for (int t2 = 0; t2 < 4; ++t2)
                ldsm4t(bl[t2][0], bl[t2][1], bl[t2][2], bl[t2][3],
                       v_s + ks * 16 * HTS * 2 + t2 * 32);
#pragma unroll
            for (int nf = 0; nf < 8; ++nf)
                mma_f16(acco[nf], a, &bl[nf >> 1][(nf & 1) * 2]);
        }
        __syncthreads();   // K/V stage reusable
    }

    // epilogue: normalize, round to tf32 (out-proj consumes it), store
#pragma unroll
    for (int rh = 0; rh < 2; ++rh) {
        float inv = 1.0f / lst[rh];
        int row = q0 + w * 16 + g + rh * 8;
        float* orow = o + (size_t)(b * S_ + row) * D_ + h * HD_;
        const int e0 = rh * 2, e1 = e0 + 1;
#pragma unroll
        for (int nf = 0; nf < 8; ++nf)
            *(float2*)(orow + nf * 8 + 2 * q) =
                make_float2(tfr(acco[nf][e0] * inv), tfr(acco[nf][e1] * inv));
    }
}

// ---------------------------------------------------------------------------
extern "C" void kernel_launch(void* const* d_in, const int* in_sizes, int n_in,
                              void* d_out, int out_size)
{
    const float* x       = (const float*)d_in[0];
    const float* Wqkv    = (const float*)d_in[1];
    const float* bqkv    = (const float*)d_in[2];
    const float* Wout    = (const float*)d_in[3];
    const float* bout    = (const float*)d_in[4];
    const float* q_scale = (const float*)d_in[5];
    const float* k_scale = (const float*)d_in[6];
    float* out = (float*)d_out;

    __half* qkvh; cudaGetSymbolAddress((void**)&qkvh, g_qkvh);
    float* o;   cudaGetSymbolAddress((void**)&o,   g_o);
    float* xt;  cudaGetSymbolAddress((void**)&xt,  g_xt);
    float* wq;  cudaGetSymbolAddress((void**)&wq,  g_wq);
    float* wo;  cudaGetSymbolAddress((void**)&wo,  g_wo);

    cudaFuncSetAttribute((const void*)gemm_tf32<3 * D_, D_, 1>,
                         cudaFuncAttributeMaxDynamicSharedMemorySize, GEMM_SMEM);
    cudaFuncSetAttribute((const void*)gemm_tf32<D_, D_, 0>,
                         cudaFuncAttributeMaxDynamicSharedMemorySize, GEMM_SMEM);
    cudaFuncSetAttribute((const void*)attn_f16,
                         cudaFuncAttributeMaxDynamicSharedMemorySize, ATT_SMEM);

    // 0) pre-round x, pre-round+transpose weights
    cvt_kernel<<<(B_ * S_ * D_ / 4 + 255) / 256, 256>>>(x, xt, B_ * S_ * D_ / 4);
    tcvt_kernel<<<dim3(3 * D_ / 32, D_ / 32), 256>>>(Wqkv, wq, D_, 3 * D_);
    tcvt_kernel<<<dim3(D_ / 32, D_ / 32), 256>>>(Wout, wo, D_, D_);

    // 1) QKV projection + fused RMSNorm, fp16 output
    gemm_tf32<3 * D_, D_, 1><<<dim3(3 * D_ / 128, (B_ * S_) / 128), 256, GEMM_SMEM>>>(
        xt, wq, bqkv, (void*)qkvh, q_scale, k_scale);

    // 2) attention (fp16 mma, fp32 accumulate)
    attn_f16<<<dim3(S_ / 128, B_ * H_), 256, ATT_SMEM>>>(qkvh, o);

    // 3) output projection (fp32 output)
    gemm_tf32<D_, D_, 0><<<dim3(D_ / 128, (B_ * S_) / 128), 256, GEMM_SMEM>>>(
        o, wo, bout, (void*)out, q_scale, k_scale);
}

// round 8
// speedup vs baseline: 2.0863x; 1.3753x over previous
#include <cuda_runtime.h>
#include <cuda_fp16.h>
#include <math.h>

#define B_  2
#define S_  2048
#define D_  1024
#define H_  16
#define HD_ 64
#define EPS_ 1e-6f
// (1/sqrt(hd)) * log2(e), folded into q during fused rmsnorm
#define QFOLD 0.18033688011112042f

// Scratch (__device__ globals: allocation-free rule)
__device__ __half g_qkvh[B_ * S_ * 3 * D_];  // qkv fp16 (post-norm q,k)
__device__ __half g_oh [B_ * S_ * D_];       // attention out, fp16
__device__ __half g_xh [B_ * S_ * D_];       // x, fp16
__device__ __half g_wqh[3 * D_ * D_];        // Wqkv^T [3D][D], fp16
__device__ __half g_woh[D_ * D_];            // Wout^T [D][D],  fp16

// ---------------------------------------------------------------------------
__device__ __forceinline__ void mma_f16(float* c, const unsigned* a, const unsigned* b) {
    asm volatile(
        "mma.sync.aligned.m16n8k16.row.col.f32.f16.f16.f32 "
        "{%0,%1,%2,%3}, {%4,%5,%6,%7}, {%8,%9}, {%0,%1,%2,%3};"
        : "+f"(c[0]), "+f"(c[1]), "+f"(c[2]), "+f"(c[3])
        : "r"(a[0]), "r"(a[1]), "r"(a[2]), "r"(a[3]), "r"(b[0]), "r"(b[1]));
}
__device__ __forceinline__ void ldsm4(unsigned& r0, unsigned& r1, unsigned& r2,
                                      unsigned& r3, unsigned addr) {
    asm volatile("ldmatrix.sync.aligned.m8n8.x4.shared.b16 {%0,%1,%2,%3}, [%4];"
        : "=r"(r0), "=r"(r1), "=r"(r2), "=r"(r3) : "r"(addr));
}
__device__ __forceinline__ void ldsm4t(unsigned& r0, unsigned& r1, unsigned& r2,
                                       unsigned& r3, unsigned addr) {
    asm volatile("ldmatrix.sync.aligned.m8n8.x4.trans.shared.b16 {%0,%1,%2,%3}, [%4];"
        : "=r"(r0), "=r"(r1), "=r"(r2), "=r"(r3) : "r"(addr));
}
__device__ __forceinline__ unsigned sptr(const void* p) {
    return (unsigned)__cvta_generic_to_shared(p);
}
__device__ __forceinline__ void cpa16(unsigned dst, const void* src) {
    asm volatile("cp.async.cg.shared.global [%0], [%1], 16;" :: "r"(dst), "l"(src));
}
__device__ __forceinline__ void cp_commit() {
    asm volatile("cp.async.commit_group;");
}
template<int Np>
__device__ __forceinline__ void cp_wait() {
    asm volatile("cp.async.wait_group %0;" :: "n"(Np));
}

// ---------------------------------------------------------------------------
// fp16-convert a contiguous array (float4 -> half4)
__global__ void cvt_h(const float* __restrict__ in, __half* __restrict__ out, int n4) {
    int i = blockIdx.x * blockDim.x + threadIdx.x;
    if (i < n4) {
        float4 v = ((const float4*)in)[i];
        __half2 h0 = __floats2half2_rn(v.x, v.y);
        __half2 h1 = __floats2half2_rn(v.z, v.w);
        ((uint2*)out)[i] = make_uint2(*(unsigned*)&h0, *(unsigned*)&h1);
    }
}

// fp16-convert + transpose: in[K][N] float -> out[N][K] half
__global__ __launch_bounds__(256) void tcvt_h(
    const float* __restrict__ in, __half* __restrict__ out, int K, int N)
{
    __shared__ float t[32][33];
    int n0 = blockIdx.x * 32, k0 = blockIdx.y * 32;
    int tx = threadIdx.x & 31, ty = threadIdx.x >> 5;
#pragma unroll
    for (int r = ty; r < 32; r += 8)
        t[r][tx] = in[(size_t)(k0 + r) * N + n0 + tx];
    __syncthreads();
#pragma unroll
    for (int r = ty; r < 32; r += 8)
        out[(size_t)(n0 + r) * K + k0 + tx] = __float2half_rn(t[tx][r]);
}

// ---------------------------------------------------------------------------
// FP16 GEMM + bias (fp32 accumulate). MODE==1: fused per-head RMSNorm, fp16 out.
// C[M,N] = A[M,K] @ Bt^T + bias ; Bt is [N][K] (pre-transposed, fp16).
// 128x128x64 tile, 8 warps, warp 32x64, m16n8k16. cp.async 3-stage.
// ---------------------------------------------------------------------------
#define GHS 72                      // halves per smem row (144B, conflict-free)
#define GSTG (128 * GHS * 2)        // bytes per stage per operand
#define GEMM_SMEM (6 * GSTG)        // 110592 B -> 2 CTAs/SM

template<int N, int K, int MODE>
__global__ __launch_bounds__(256, 2) void gemm_f16(
    const __half* __restrict__ A, const __half* __restrict__ Bt,
    const float* __restrict__ bias, void* __restrict__ Cv,
    const float* __restrict__ q_scale, const float* __restrict__ k_scale)
{
    extern __shared__ __half smh[];
    __half* As = smh;                    // 3 stages x 128*GHS
    __half* Bs = smh + 3 * 128 * GHS;    // 3 stages x 128*GHS

    const int tid = threadIdx.x;
    const int lane = tid & 31;
    const int wid = tid >> 5;
    const int g = lane >> 2;
    const int q = lane & 3;
    const int wm = wid >> 1;
    const int wn = wid & 1;
    const int bxn = blockIdx.x * 128;
    const int bym = blockIdx.y * 128;

    // copy mapping: idx -> (row 0..127, 16B-chunk 0..7); both operands [row][k]
    const __half* asrc[4]; const __half* bsrc[4];
    unsigned adst[4], bdst[4];
#pragma unroll
    for (int i = 0; i < 4; ++i) {
        int idx = tid + 256 * i, r = idx >> 3, c = idx & 7;
        asrc[i] = A  + (size_t)(bym + r) * K + c * 8;
        bsrc[i] = Bt + (size_t)(bxn + r) * K + c * 8;
        adst[i] = sptr(As) + (r * GHS + c * 8) * 2;
        bdst[i] = sptr(Bs) + (r * GHS + c * 8) * 2;
    }

    const unsigned a_base = sptr(As) + ((wm * 32 + (lane & 15)) * GHS) * 2 + (lane >> 4) * 16;
    const unsigned b_base = sptr(Bs) + ((wn * 64 + (lane & 7) + ((lane >> 4) << 3)) * GHS) * 2
                          + ((lane >> 3) & 1) * 16;

    float acc[2][8][4];
#pragma unroll
    for (int mf = 0; mf < 2; ++mf)
#pragma unroll
        for (int nf = 0; nf < 8; ++nf)
#pragma unroll
            for (int e = 0; e < 4; ++e) acc[mf][nf][e] = 0.f;

    const int KT = K / 64;

    // prologue: stages 0 and 1
#pragma unroll
    for (int i = 0; i < 4; ++i) { cpa16(adst[i], asrc[i]); cpa16(bdst[i], bsrc[i]); }
    cp_commit();
#pragma unroll
    for (int i = 0; i < 4; ++i) {
        cpa16(adst[i] + GSTG, asrc[i] + 64);
        cpa16(bdst[i] + GSTG, bsrc[i] + 64);
    }
    cp_commit();

    for (int kt = 0; kt < KT; ++kt) {
        if (kt + 2 < KT) {
            const int koff = (kt + 2) * 64;
            const unsigned so = ((kt + 2) % 3) * GSTG;
#pragma unroll
            for (int i = 0; i < 4; ++i) {
                cpa16(adst[i] + so, asrc[i] + koff);
                cpa16(bdst[i] + so, bsrc[i] + koff);
            }
            cp_commit();
            cp_wait<2>();
        } else if (kt + 2 == KT) {
            cp_wait<1>();
        } else {
            cp_wait<0>();
        }
        __syncthreads();

        const unsigned a_s = a_base + (kt % 3) * GSTG;
        const unsigned b_s = b_base + (kt % 3) * GSTG;
#pragma unroll
        for (int ks = 0; ks < 4; ++ks) {
            unsigned a0[4], a1[4], bl[4][4];
            ldsm4(a0[0], a0[1], a0[2], a0[3], a_s + ks * 32);
            ldsm4(a1[0], a1[1], a1[2], a1[3], a_s + 16 * GHS * 2 + ks * 32);
#pragma unroll
            for (int t2 = 0; t2 < 4; ++t2)
                ldsm4(bl[t2][0], bl[t2][1], bl[t2][2], bl[t2][3],
                      b_s + t2 * 16 * GHS * 2 + ks * 32);
#pragma unroll
            for (int nf = 0; nf < 8; ++nf) {
                const unsigned* bf = &bl[nf >> 1][(nf & 1) * 2];
                mma_f16(acc[0][nf], a0, bf);
                mma_f16(acc[1][nf], a1, bf);
            }
        }
        __syncthreads();   // stage reusable
    }

    // epilogue
    const bool donorm = (MODE == 1) && (bxn < 2048);
    const float* sc = (bxn < 1024) ? q_scale : k_scale;
    const float fold = (bxn < 1024) ? QFOLD : 1.0f;

#pragma unroll
    for (int mf = 0; mf < 2; ++mf) {
        int r0 = bym + wm * 32 + mf * 16 + g;
#pragma unroll
        for (int nf = 0; nf < 8; ++nf) {
            int col = bxn + wn * 64 + nf * 8 + 2 * q;
            float2 bs = *(const float2*)(bias + col);
            acc[mf][nf][0] += bs.x; acc[mf][nf][1] += bs.y;
            acc[mf][nf][2] += bs.x; acc[mf][nf][3] += bs.y;
        }
        if (donorm) {
#pragma unroll
            for (int rh = 0; rh < 2; ++rh) {
                const int e0 = rh * 2, e1 = e0 + 1;
                float ss = 0.f;
#pragma unroll
                for (int nf = 0; nf < 8; ++nf)
                    ss += acc[mf][nf][e0] * acc[mf][nf][e0]
                        + acc[mf][nf][e1] * acc[mf][nf][e1];
                ss += __shfl_xor_sync(0xffffffffu, ss, 1);
                ss += __shfl_xor_sync(0xffffffffu, ss, 2);
                float rr = rsqrtf(ss * (1.0f / HD_) + EPS_) * fold;
#pragma unroll
                for (int nf = 0; nf < 8; ++nf) {
                    float2 s2 = *(const float2*)(sc + nf * 8 + 2 * q);
                    acc[mf][nf][e0] *= rr * s2.x;
                    acc[mf][nf][e1] *= rr * s2.y;
                }
            }
        }
#pragma unroll
        for (int nf = 0; nf < 8; ++nf) {
            int col = bxn + wn * 64 + nf * 8 + 2 * q;
            if (MODE == 1) {
                __half* Ch = (__half*)Cv;
                *(__half2*)(Ch + (size_t)r0 * N + col) =
                    __floats2half2_rn(acc[mf][nf][0], acc[mf][nf][1]);
                *(__half2*)(Ch + (size_t)(r0 + 8) * N + col) =
                    __floats2half2_rn(acc[mf][nf][2], acc[mf][nf][3]);
            } else {
                float* Cf = (float*)Cv;
                *(float2*)(Cf + (size_t)r0 * N + col) =
                    make_float2(acc[mf][nf][0], acc[mf][nf][1]);
                *(float2*)(Cf + (size_t)(r0 + 8) * N + col) =
                    make_float2(acc[mf][nf][2], acc[mf][nf][3]);
            }
        }
    }
}

// ---------------------------------------------------------------------------
// FP16 flash attention (fp32 accumulate). CTA: 256 thr (8 warps), 128 queries,
// warp = 16 q-rows x 64 keys. cp.async double-buffered K/V. Output fp16.
// ---------------------------------------------------------------------------
#define HTS 72
#define OFK (128 * HTS)
#define OFV (OFK + 2 * 64 * HTS)
#define OFP (OFV + 2 * 64 * HTS)
#define KVSTG (64 * HTS * 2)
#define ATT_SMEM ((OFP + 128 * HTS) * 2)

__global__ __launch_bounds__(256, 2) void attn_f16(
    const __half* __restrict__ qkv, __half* __restrict__ o)
{
    extern __shared__ __half smh[];
    __half* Qh = smh;
    __half* Kh = smh + OFK;
    __half* Vh = smh + OFV;
    __half* Ph = smh + OFP;

    const int tid = threadIdx.x;
    const int lane = tid & 31;
    const int w = tid >> 5;
    const int g = lane >> 2;
    const int q = lane & 3;
    const int q0 = blockIdx.x * 128;
    const int bh = blockIdx.y;
    const int b = bh >> 4;
    const int h = bh & 15;

    const __half* base = qkv + (size_t)b * S_ * 3 * D_ + h * HD_;

    // K/V copy mapping: 2 x 16B chunks each (64 rows x 8 chunks)
    const __half* ksrc[2]; const __half* vsrc[2];
    unsigned kdst[2], vdst[2];
#pragma unroll
    for (int i = 0; i < 2; ++i) {
        int idx = tid + 256 * i, r = idx >> 3, c = idx & 7;
        ksrc[i] = base + (size_t)r * (3 * D_) + D_ + c * 8;
        vsrc[i] = base + (size_t)r * (3 * D_) + 2 * D_ + c * 8;
        kdst[i] = sptr(Kh) + (r * HTS + c * 8) * 2;
        vdst[i] = sptr(Vh) + (r * HTS + c * 8) * 2;
    }

    // prologue: Q (128 rows x 8 chunks) + K/V tile 0, one commit group
#pragma unroll
    for (int i = 0; i < 4; ++i) {
        int idx = tid + 256 * i, r = idx >> 3, c = idx & 7;
        cpa16(sptr(Qh) + (r * HTS + c * 8) * 2,
              base + (size_t)(q0 + r) * (3 * D_) + c * 8);
    }
#pragma unroll
    for (int i = 0; i < 2; ++i) { cpa16(kdst[i], ksrc[i]); cpa16(vdst[i], vsrc[i]); }
    cp_commit();

    const unsigned arow = ((w * 16 + (lane & 15)) * HTS) * 2 + (lane >> 4) * 16;
    const unsigned qbase = sptr(Qh) + arow;
    const unsigned pbase = sptr(Ph) + arow;
    const unsigned kbase = sptr(Kh)
        + (((lane & 7) + ((lane >> 4) << 3)) * HTS) * 2 + ((lane >> 3) & 1) * 16;
    const unsigned vbase = sptr(Vh)
        + (((lane & 7) + (((lane >> 3) & 1) << 3)) * HTS) * 2 + (lane >> 4) * 16;

    float mst[2] = {-1e30f, -1e30f}, lst[2] = {0.f, 0.f};
    float acco[8][4];
#pragma unroll
    for (int nf = 0; nf < 8; ++nf)
#pragma unroll
        for (int e = 0; e < 4; ++e) acco[nf][e] = 0.f;

    const int T = S_ / 64;
    for (int t = 0; t < T; ++t) {
        if (t + 1 < T) {
            const size_t ko = (size_t)(t + 1) * 64 * (3 * D_);
            const unsigned so = ((t + 1) & 1) * KVSTG;
#pragma unroll
            for (int i = 0; i < 2; ++i) {
                cpa16(kdst[i] + so, ksrc[i] + ko);
                cpa16(vdst[i] + so, vsrc[i] + ko);
            }
            cp_commit();
            cp_wait<1>();
        } else {
            cp_wait<0>();
        }
        __syncthreads();

        const unsigned k_s = kbase + (t & 1) * KVSTG;
        const unsigned v_s = vbase + (t & 1) * KVSTG;

        // S = Q K^T
        float accs[8][4];
#pragma unroll
        for (int nf = 0; nf < 8; ++nf)
#pragma unroll
            for (int e = 0; e < 4; ++e) accs[nf][e] = 0.f;
#pragma unroll
        for (int ks = 0; ks < 4; ++ks) {
            unsigned a[4], bl[4][4];
            ldsm4(a[0], a[1], a[2], a[3], qbase + ks * 32);
#pragma unroll
            for (int t2 = 0; t2 < 4; ++t2)
                ldsm4(bl[t2][0], bl[t2][1], bl[t2][2], bl[t2][3],
                      k_s + t2 * 16 * HTS * 2 + ks * 32);
#pragma unroll
            for (int nf = 0; nf < 8; ++nf)
                mma_f16(accs[nf], a, &bl[nf >> 1][(nf & 1) * 2]);
        }

        // online softmax (rows in quads)
#pragma unroll
        for (int rh = 0; rh < 2; ++rh) {
            const int e0 = rh * 2, e1 = e0 + 1;
            float mold = mst[rh];
            float mx = mold;
#pragma unroll
            for (int nf = 0; nf < 8; ++nf)
                mx = fmaxf(mx, fmaxf(accs[nf][e0], accs[nf][e1]));
            mx = fmaxf(mx, __shfl_xor_sync(0xffffffffu, mx, 1));
            mx = fmaxf(mx, __shfl_xor_sync(0xffffffffu, mx, 2));
            float corr = exp2f(mold - mx);
            mst[rh] = mx;
            float sum = 0.f;
            int rowb = (w * 16 + g + rh * 8) * HTS + 2 * q;
#pragma unroll
            for (int nf = 0; nf < 8; ++nf) {
                float p0 = exp2f(accs[nf][e0] - mx);
                float p1 = exp2f(accs[nf][e1] - mx);
                sum += p0 + p1;
                *(__half2*)(Ph + rowb + nf * 8) = __floats2half2_rn(p0, p1);
                acco[nf][e0] *= corr;
                acco[nf][e1] *= corr;
            }
            sum += __shfl_xor_sync(0xffffffffu, sum, 1);
            sum += __shfl_xor_sync(0xffffffffu, sum, 2);
            lst[rh] = lst[rh] * corr + sum;
        }
        __syncwarp();   // P is warp-private

        // O += P V  (V B-frags via ldmatrix.trans)
#pragma unroll
        for (int ks = 0; ks < 4; ++ks) {
            unsigned a[4], bl[4][4];
            ldsm4(a[0], a[1], a[2], a[3], pbase + ks * 32);
#pragma unroll
            for (int t2 = 0; t2 < 4; ++t2)
                ldsm4t(bl[t2][0], bl[t2][1], bl[t2][2], bl[t2][3],
                       v_s + ks * 16 * HTS * 2 + t2 * 32);
#pragma unroll
            for (int nf = 0; nf < 8; ++nf)
                mma_f16(acco[nf], a, &bl[nf >> 1][(nf & 1) * 2]);
        }
        __syncthreads();   // K/V stage reusable
    }

    // epilogue: normalize, store fp16 (consumed by fp16 out-proj)
#pragma unroll
    for (int rh = 0; rh < 2; ++rh) {
        float inv = 1.0f / lst[rh];
        int row = q0 + w * 16 + g + rh * 8;
        __half* orow = o + (size_t)(b * S_ + row) * D_ + h * HD_;
        const int e0 = rh * 2, e1 = e0 + 1;
#pragma unroll
        for (int nf = 0; nf < 8; ++nf)
            *(__half2*)(orow + nf * 8 + 2 * q) =
                __floats2half2_rn(acco[nf][e0] * inv, acco[nf][e1] * inv);
    }
}

// ---------------------------------------------------------------------------
extern "C" void kernel_launch(void* const* d_in, const int* in_sizes, int n_in,
                              void* d_out, int out_size)
{
    const float* x       = (const float*)d_in[0];
    const float* Wqkv    = (const float*)d_in[1];
    const float* bqkv    = (const float*)d_in[2];
    const float* Wout    = (const float*)d_in[3];
    const float* bout    = (const float*)d_in[4];
    const float* q_scale = (const float*)d_in[5];
    const float* k_scale = (const float*)d_in[6];
    float* out = (float*)d_out;

    __half* qkvh; cudaGetSymbolAddress((void**)&qkvh, g_qkvh);
    __half* oh;   cudaGetSymbolAddress((void**)&oh,   g_oh);
    __half* xh;   cudaGetSymbolAddress((void**)&xh,   g_xh);
    __half* wqh;  cudaGetSymbolAddress((void**)&wqh,  g_wqh);
    __half* woh;  cudaGetSymbolAddress((void**)&woh,  g_woh);

    cudaFuncSetAttribute((const void*)gemm_f16<3 * D_, D_, 1>,
                         cudaFuncAttributeMaxDynamicSharedMemorySize, GEMM_SMEM);
    cudaFuncSetAttribute((const void*)gemm_f16<D_, D_, 0>,
                         cudaFuncAttributeMaxDynamicSharedMemorySize, GEMM_SMEM);
    cudaFuncSetAttribute((const void*)attn_f16,
                         cudaFuncAttributeMaxDynamicSharedMemorySize, ATT_SMEM);

    // 0) pre-convert x + weights to fp16 (weights transposed)
    cvt_h<<<(B_ * S_ * D_ / 4 + 255) / 256, 256>>>(x, xh, B_ * S_ * D_ / 4);
    tcvt_h<<<dim3(3 * D_ / 32, D_ / 32), 256>>>(Wqkv, wqh, D_, 3 * D_);
    tcvt_h<<<dim3(D_ / 32, D_ / 32), 256>>>(Wout, woh, D_, D_);

    // 1) QKV projection + fused RMSNorm, fp16 output
    gemm_f16<3 * D_, D_, 1><<<dim3(3 * D_ / 128, (B_ * S_) / 128), 256, GEMM_SMEM>>>(
        xh, wqh, bqkv, (void*)qkvh, q_scale, k_scale);

    // 2) attention (fp16 mma, fp32 accumulate), fp16 output
    attn_f16<<<dim3(S_ / 128, B_ * H_), 256, ATT_SMEM>>>(qkvh, oh);

    // 3) output projection (fp32 output)
    gemm_f16<D_, D_, 0><<<dim3(D_ / 128, (B_ * S_) / 128), 256, GEMM_SMEM>>>(
        oh, woh, bout, (void*)out, q_scale, k_scale);
}

// round 9
// speedup vs baseline: 2.1015x; 1.0073x over previous
#include <cuda_runtime.h>
#include <cuda_fp16.h>
#include <math.h>

#define B_  2
#define S_  2048
#define D_  1024
#define H_  16
#define HD_ 64
#define EPS_ 1e-6f
// (1/sqrt(hd)) * log2(e), folded into q during fused rmsnorm
#define QFOLD 0.18033688011112042f

// Scratch (__device__ globals: allocation-free rule)
__device__ __half g_qkvh[B_ * S_ * 3 * D_];  // qkv fp16 (post-norm q,k)
__device__ __half g_oh [B_ * S_ * D_];       // attention out, fp16
__device__ __half g_xh [B_ * S_ * D_];       // x, fp16
__device__ __half g_wqh[3 * D_ * D_];        // Wqkv^T [3D][D], fp16
__device__ __half g_woh[D_ * D_];            // Wout^T [D][D],  fp16

// ---------------------------------------------------------------------------
__device__ __forceinline__ void mma_f16(float* c, const unsigned* a, const unsigned* b) {
    asm volatile(
        "mma.sync.aligned.m16n8k16.row.col.f32.f16.f16.f32 "
        "{%0,%1,%2,%3}, {%4,%5,%6,%7}, {%8,%9}, {%0,%1,%2,%3};"
        : "+f"(c[0]), "+f"(c[1]), "+f"(c[2]), "+f"(c[3])
        : "r"(a[0]), "r"(a[1]), "r"(a[2]), "r"(a[3]), "r"(b[0]), "r"(b[1]));
}
__device__ __forceinline__ void ldsm4(unsigned& r0, unsigned& r1, unsigned& r2,
                                      unsigned& r3, unsigned addr) {
    asm volatile("ldmatrix.sync.aligned.m8n8.x4.shared.b16 {%0,%1,%2,%3}, [%4];"
        : "=r"(r0), "=r"(r1), "=r"(r2), "=r"(r3) : "r"(addr));
}
__device__ __forceinline__ void ldsm4t(unsigned& r0, unsigned& r1, unsigned& r2,
                                       unsigned& r3, unsigned addr) {
    asm volatile("ldmatrix.sync.aligned.m8n8.x4.trans.shared.b16 {%0,%1,%2,%3}, [%4];"
        : "=r"(r0), "=r"(r1), "=r"(r2), "=r"(r3) : "r"(addr));
}
__device__ __forceinline__ unsigned sptr(const void* p) {
    return (unsigned)__cvta_generic_to_shared(p);
}
__device__ __forceinline__ void cpa16(unsigned dst, const void* src) {
    asm volatile("cp.async.cg.shared.global [%0], [%1], 16;" :: "r"(dst), "l"(src));
}
__device__ __forceinline__ void cp_commit() {
    asm volatile("cp.async.commit_group;");
}
template<int Np>
__device__ __forceinline__ void cp_wait() {
    asm volatile("cp.async.wait_group %0;" :: "n"(Np));
}

// ---------------------------------------------------------------------------
// fp16-convert a contiguous array (float4 -> half4)
__global__ void cvt_h(const float* __restrict__ in, __half* __restrict__ out, int n4) {
    int i = blockIdx.x * blockDim.x + threadIdx.x;
    if (i < n4) {
        float4 v = ((const float4*)in)[i];
        __half2 h0 = __floats2half2_rn(v.x, v.y);
        __half2 h1 = __floats2half2_rn(v.z, v.w);
        ((uint2*)out)[i] = make_uint2(*(unsigned*)&h0, *(unsigned*)&h1);
    }
}

// fp16-convert + transpose: in[K][N] float -> out[N][K] half
__global__ __launch_bounds__(256) void tcvt_h(
    const float* __restrict__ in, __half* __restrict__ out, int K, int N)
{
    __shared__ float t[32][33];
    int n0 = blockIdx.x * 32, k0 = blockIdx.y * 32;
    int tx = threadIdx.x & 31, ty = threadIdx.x >> 5;
#pragma unroll
    for (int r = ty; r < 32; r += 8)
        t[r][tx] = in[(size_t)(k0 + r) * N + n0 + tx];
    __syncthreads();
#pragma unroll
    for (int r = ty; r < 32; r += 8)
        out[(size_t)(n0 + r) * K + k0 + tx] = __float2half_rn(t[tx][r]);
}

// ---------------------------------------------------------------------------
// FP16 GEMM + bias (fp32 accumulate). MODE==1: fused per-head RMSNorm, fp16 out.
// C[M,N] = A[M,K] @ Bt^T + bias ; Bt is [N][K] (pre-transposed, fp16).
// 128x128x64 tile, 8 warps, warp 32x64, m16n8k16. cp.async 3-stage,
// SINGLE barrier per iteration (prefetch issued after the barrier).
// ---------------------------------------------------------------------------
#define GHS 72                      // halves per smem row (144B, conflict-free)
#define GSTG (128 * GHS * 2)        // bytes per stage per operand
#define GEMM_SMEM (6 * GSTG)        // 110592 B -> 2 CTAs/SM

template<int N, int K, int MODE>
__global__ __launch_bounds__(256, 2) void gemm_f16(
    const __half* __restrict__ A, const __half* __restrict__ Bt,
    const float* __restrict__ bias, void* __restrict__ Cv,
    const float* __restrict__ q_scale, const float* __restrict__ k_scale)
{
    extern __shared__ __half smh[];
    __half* As = smh;                    // 3 stages x 128*GHS
    __half* Bs = smh + 3 * 128 * GHS;    // 3 stages x 128*GHS

    const int tid = threadIdx.x;
    const int lane = tid & 31;
    const int wid = tid >> 5;
    const int g = lane >> 2;
    const int q = lane & 3;
    const int wm = wid >> 1;
    const int wn = wid & 1;
    const int bxn = blockIdx.x * 128;
    const int bym = blockIdx.y * 128;

    // copy mapping: idx -> (row 0..127, 16B-chunk 0..7); both operands [row][k]
    const __half* asrc[4]; const __half* bsrc[4];
    unsigned adst[4], bdst[4];
#pragma unroll
    for (int i = 0; i < 4; ++i) {
        int idx = tid + 256 * i, r = idx >> 3, c = idx & 7;
        asrc[i] = A  + (size_t)(bym + r) * K + c * 8;
        bsrc[i] = Bt + (size_t)(bxn + r) * K + c * 8;
        adst[i] = sptr(As) + (r * GHS + c * 8) * 2;
        bdst[i] = sptr(Bs) + (r * GHS + c * 8) * 2;
    }

    const unsigned a_base = sptr(As) + ((wm * 32 + (lane & 15)) * GHS) * 2 + (lane >> 4) * 16;
    const unsigned b_base = sptr(Bs) + ((wn * 64 + (lane & 7) + ((lane >> 4) << 3)) * GHS) * 2
                          + ((lane >> 3) & 1) * 16;

    float acc[2][8][4];
#pragma unroll
    for (int mf = 0; mf < 2; ++mf)
#pragma unroll
        for (int nf = 0; nf < 8; ++nf)
#pragma unroll
            for (int e = 0; e < 4; ++e) acc[mf][nf][e] = 0.f;

    const int KT = K / 64;

    // prologue: stages 0 and 1 (two commit groups)
#pragma unroll
    for (int i = 0; i < 4; ++i) { cpa16(adst[i], asrc[i]); cpa16(bdst[i], bsrc[i]); }
    cp_commit();
#pragma unroll
    for (int i = 0; i < 4; ++i) {
        cpa16(adst[i] + GSTG, asrc[i] + 64);
        cpa16(bdst[i] + GSTG, bsrc[i] + 64);
    }
    cp_commit();

    for (int kt = 0; kt < KT; ++kt) {
        // ensure stage kt landed (one younger group may stay in flight)
        if (kt + 1 < KT) cp_wait<1>(); else cp_wait<0>();
        __syncthreads();   // also proves all warps finished compute of kt-1
        // prefetch stage kt+2 (overwrites stage kt-1, freed by the barrier)
        if (kt + 2 < KT) {
            const int koff = (kt + 2) * 64;
            const unsigned so = ((kt + 2) % 3) * GSTG;
#pragma unroll
            for (int i = 0; i < 4; ++i) {
                cpa16(adst[i] + so, asrc[i] + koff);
                cpa16(bdst[i] + so, bsrc[i] + koff);
            }
            cp_commit();
        }

        const unsigned a_s = a_base + (kt % 3) * GSTG;
        const unsigned b_s = b_base + (kt % 3) * GSTG;
#pragma unroll
        for (int ks = 0; ks < 4; ++ks) {
            unsigned a0[4], a1[4], bl[4][4];
            ldsm4(a0[0], a0[1], a0[2], a0[3], a_s + ks * 32);
            ldsm4(a1[0], a1[1], a1[2], a1[3], a_s + 16 * GHS * 2 + ks * 32);
#pragma unroll
            for (int t2 = 0; t2 < 4; ++t2)
                ldsm4(bl[t2][0], bl[t2][1], bl[t2][2], bl[t2][3],
                      b_s + t2 * 16 * GHS * 2 + ks * 32);
#pragma unroll
            for (int nf = 0; nf < 8; ++nf) {
                const unsigned* bf = &bl[nf >> 1][(nf & 1) * 2];
                mma_f16(acc[0][nf], a0, bf);
                mma_f16(acc[1][nf], a1, bf);
            }
        }
    }

    // epilogue
    const bool donorm = (MODE == 1) && (bxn < 2048);
    const float* sc = (bxn < 1024) ? q_scale : k_scale;
    const float fold = (bxn < 1024) ? QFOLD : 1.0f;

#pragma unroll
    for (int mf = 0; mf < 2; ++mf) {
        int r0 = bym + wm * 32 + mf * 16 + g;
#pragma unroll
        for (int nf = 0; nf < 8; ++nf) {
            int col = bxn + wn * 64 + nf * 8 + 2 * q;
            float2 bs = *(const float2*)(bias + col);
            acc[mf][nf][0] += bs.x; acc[mf][nf][1] += bs.y;
            acc[mf][nf][2] += bs.x; acc[mf][nf][3] += bs.y;
        }
        if (donorm) {
#pragma unroll
            for (int rh = 0; rh < 2; ++rh) {
                const int e0 = rh * 2, e1 = e0 + 1;
                float ss = 0.f;
#pragma unroll
                for (int nf = 0; nf < 8; ++nf)
                    ss += acc[mf][nf][e0] * acc[mf][nf][e0]
                        + acc[mf][nf][e1] * acc[mf][nf][e1];
                ss += __shfl_xor_sync(0xffffffffu, ss, 1);
                ss += __shfl_xor_sync(0xffffffffu, ss, 2);
                float rr = rsqrtf(ss * (1.0f / HD_) + EPS_) * fold;
#pragma unroll
                for (int nf = 0; nf < 8; ++nf) {
                    float2 s2 = *(const float2*)(sc + nf * 8 + 2 * q);
                    acc[mf][nf][e0] *= rr * s2.x;
                    acc[mf][nf][e1] *= rr * s2.y;
                }
            }
        }
#pragma unroll
        for (int nf = 0; nf < 8; ++nf) {
            int col = bxn + wn * 64 + nf * 8 + 2 * q;
            if (MODE == 1) {
                __half* Ch = (__half*)Cv;
                *(__half2*)(Ch + (size_t)r0 * N + col) =
                    __floats2half2_rn(acc[mf][nf][0], acc[mf][nf][1]);
                *(__half2*)(Ch + (size_t)(r0 + 8) * N + col) =
                    __floats2half2_rn(acc[mf][nf][2], acc[mf][nf][3]);
            } else {
                float* Cf = (float*)Cv;
                *(float2*)(Cf + (size_t)r0 * N + col) =
                    make_float2(acc[mf][nf][0], acc[mf][nf][1]);
                *(float2*)(Cf + (size_t)(r0 + 8) * N + col) =
                    make_float2(acc[mf][nf][2], acc[mf][nf][3]);
            }
        }
    }
}

// ---------------------------------------------------------------------------
// FP16 flash attention (fp32 accumulate). CTA: 256 thr (8 warps), 128 queries,
// warp = 16 q-rows x 64 keys. cp.async double-buffered K/V, SINGLE barrier
// per KV tile (prefetch issued after the barrier). Output fp16.
// ---------------------------------------------------------------------------
#define HTS 72
#define OFK (128 * HTS)
#define OFV (OFK + 2 * 64 * HTS)
#define OFP (OFV + 2 * 64 * HTS)
#define KVSTG (64 * HTS * 2)
#define ATT_SMEM ((OFP + 128 * HTS) * 2)

__global__ __launch_bounds__(256, 2) void attn_f16(
    const __half* __restrict__ qkv, __half* __restrict__ o)
{
    extern __shared__ __half smh[];
    __half* Qh = smh;
    __half* Kh = smh + OFK;
    __half* Vh = smh + OFV;
    __half* Ph = smh + OFP;

    const int tid = threadIdx.x;
    const int lane = tid & 31;
    const int w = tid >> 5;
    const int g = lane >> 2;
    const int q = lane & 3;
    const int q0 = blockIdx.x * 128;
    const int bh = blockIdx.y;
    const int b = bh >> 4;
    const int h = bh & 15;

    const __half* base = qkv + (size_t)b * S_ * 3 * D_ + h * HD_;

    // K/V copy mapping: 2 x 16B chunks each (64 rows x 8 chunks)
    const __half* ksrc[2]; const __half* vsrc[2];
    unsigned kdst[2], vdst[2];
#pragma unroll
    for (int i = 0; i < 2; ++i) {
        int idx = tid + 256 * i, r = idx >> 3, c = idx & 7;
        ksrc[i] = base + (size_t)r * (3 * D_) + D_ + c * 8;
        vsrc[i] = base + (size_t)r * (3 * D_) + 2 * D_ + c * 8;
        kdst[i] = sptr(Kh) + (r * HTS + c * 8) * 2;
        vdst[i] = sptr(Vh) + (r * HTS + c * 8) * 2;
    }

    // prologue: Q (128 rows x 8 chunks) + K/V tile 0, one commit group
#pragma unroll
    for (int i = 0; i < 4; ++i) {
        int idx = tid + 256 * i, r = idx >> 3, c = idx & 7;
        cpa16(sptr(Qh) + (r * HTS + c * 8) * 2,
              base + (size_t)(q0 + r) * (3 * D_) + c * 8);
    }
#pragma unroll
    for (int i = 0; i < 2; ++i) { cpa16(kdst[i], ksrc[i]); cpa16(vdst[i], vsrc[i]); }
    cp_commit();

    const unsigned arow = ((w * 16 + (lane & 15)) * HTS) * 2 + (lane >> 4) * 16;
    const unsigned qbase = sptr(Qh) + arow;
    const unsigned pbase = sptr(Ph) + arow;
    const unsigned kbase = sptr(Kh)
        + (((lane & 7) + ((lane >> 4) << 3)) * HTS) * 2 + ((lane >> 3) & 1) * 16;
    const unsigned vbase = sptr(Vh)
        + (((lane & 7) + (((lane >> 3) & 1) << 3)) * HTS) * 2 + (lane >> 4) * 16;

    float mst[2] = {-1e30f, -1e30f}, lst[2] = {0.f, 0.f};
    float acco[8][4];
#pragma unroll
    for (int nf = 0; nf < 8; ++nf)
#pragma unroll
        for (int e = 0; e < 4; ++e) acco[nf][e] = 0.f;

    const int T = S_ / 64;
    for (int t = 0; t < T; ++t) {
        cp_wait<0>();      // stage t landed (had full tile t-1 compute to cover)
        __syncthreads();   // all warps done with stage t-1 (now overwritable)
        if (t + 1 < T) {   // prefetch stage (t+1)&1 == (t-1)&1
            const size_t ko = (size_t)(t + 1) * 64 * (3 * D_);
            const unsigned so = ((t + 1) & 1) * KVSTG;
#pragma unroll
            for (int i = 0; i < 2; ++i) {
                cpa16(kdst[i] + so, ksrc[i] + ko);
                cpa16(vdst[i] + so, vsrc[i] + ko);
            }
            cp_commit();
        }

        const unsigned k_s = kbase + (t & 1) * KVSTG;
        const unsigned v_s = vbase + (t & 1) * KVSTG;

        // S = Q K^T
        float accs[8][4];
#pragma unroll
        for (int nf = 0; nf < 8; ++nf)
#pragma unroll
            for (int e = 0; e < 4; ++e) accs[nf][e] = 0.f;
#pragma unroll
        for (int ks = 0; ks < 4; ++ks) {
            unsigned a[4], bl[4][4];
            ldsm4(a[0], a[1], a[2], a[3], qbase + ks * 32);
#pragma unroll
            for (int t2 = 0; t2 < 4; ++t2)
                ldsm4(bl[t2][0], bl[t2][1], bl[t2][2], bl[t2][3],
                      k_s + t2 * 16 * HTS * 2 + ks * 32);
#pragma unroll
            for (int nf = 0; nf < 8; ++nf)
                mma_f16(accs[nf], a, &bl[nf >> 1][(nf & 1) * 2]);
        }

        // online softmax (rows in quads)
#pragma unroll
        for (int rh = 0; rh < 2; ++rh) {
            const int e0 = rh * 2, e1 = e0 + 1;
            float mold = mst[rh];
            float mx = mold;
#pragma unroll
            for (int nf = 0; nf < 8; ++nf)
                mx = fmaxf(mx, fmaxf(accs[nf][e0], accs[nf][e1]));
            mx = fmaxf(mx, __shfl_xor_sync(0xffffffffu, mx, 1));
            mx = fmaxf(mx, __shfl_xor_sync(0xffffffffu, mx, 2));
            float corr = exp2f(mold - mx);
            mst[rh] = mx;
            float sum = 0.f;
            int rowb = (w * 16 + g + rh * 8) * HTS + 2 * q;
#pragma unroll
            for (int nf = 0; nf < 8; ++nf) {
                float p0 = exp2f(accs[nf][e0] - mx);
                float p1 = exp2f(accs[nf][e1] - mx);
                sum += p0 + p1;
                *(__half2*)(Ph + rowb + nf * 8) = __floats2half2_rn(p0, p1);
                acco[nf][e0] *= corr;
                acco[nf][e1] *= corr;
            }
            sum += __shfl_xor_sync(0xffffffffu, sum, 1);
            sum += __shfl_xor_sync(0xffffffffu, sum, 2);
            lst[rh] = lst[rh] * corr + sum;
        }
        __syncwarp();   // P is warp-private

        // O += P V  (V B-frags via ldmatrix.trans)
#pragma unroll
        for (int ks = 0; ks < 4; ++ks) {
            unsigned a[4], bl[4][4];
            ldsm4(a[0], a[1], a[2], a[3], pbase + ks * 32);
#pragma unroll
            for (int t2 = 0; t2 < 4; ++t2)
                ldsm4t(bl[t2][0], bl[t2][1], bl[t2][2], bl[t2][3],
                       v_s + ks * 16 * HTS * 2 + t2 * 32);
#pragma unroll
            for (int nf = 0; nf < 8; ++nf)
                mma_f16(acco[nf], a, &bl[nf >> 1][(nf & 1) * 2]);
        }
    }

    // epilogue: normalize, store fp16 (consumed by fp16 out-proj)
#pragma unroll
    for (int rh = 0; rh < 2; ++rh) {
        float inv = 1.0f / lst[rh];
        int row = q0 + w * 16 + g + rh * 8;
        __half* orow = o + (size_t)(b * S_ + row) * D_ + h * HD_;
        const int e0 = rh * 2, e1 = e0 + 1;
#pragma unroll
        for (int nf = 0; nf < 8; ++nf)
            *(__half2*)(orow + nf * 8 + 2 * q) =
                __floats2half2_rn(acco[nf][e0] * inv, acco[nf][e1] * inv);
    }
}

// ---------------------------------------------------------------------------
extern "C" void kernel_launch(void* const* d_in, const int* in_sizes, int n_in,
                              void* d_out, int out_size)
{
    const float* x       = (const float*)d_in[0];
    const float* Wqkv    = (const float*)d_in[1];
    const float* bqkv    = (const float*)d_in[2];
    const float* Wout    = (const float*)d_in[3];
    const float* bout    = (const float*)d_in[4];
    const float* q_scale = (const float*)d_in[5];
    const float* k_scale = (const float*)d_in[6];
    float* out = (float*)d_out;

    __half* qkvh; cudaGetSymbolAddress((void**)&qkvh, g_qkvh);
    __half* oh;   cudaGetSymbolAddress((void**)&oh,   g_oh);
    __half* xh;   cudaGetSymbolAddress((void**)&xh,   g_xh);
    __half* wqh;  cudaGetSymbolAddress((void**)&wqh,  g_wqh);
    __half* woh;  cudaGetSymbolAddress((void**)&woh,  g_woh);

    cudaFuncSetAttribute((const void*)gemm_f16<3 * D_, D_, 1>,
                         cudaFuncAttributeMaxDynamicSharedMemorySize, GEMM_SMEM);
    cudaFuncSetAttribute((const void*)gemm_f16<D_, D_, 0>,
                         cudaFuncAttributeMaxDynamicSharedMemorySize, GEMM_SMEM);
    cudaFuncSetAttribute((const void*)attn_f16,
                         cudaFuncAttributeMaxDynamicSharedMemorySize, ATT_SMEM);

    // 0) pre-convert x + weights to fp16 (weights transposed)
    cvt_h<<<(B_ * S_ * D_ / 4 + 255) / 256, 256>>>(x, xh, B_ * S_ * D_ / 4);
    tcvt_h<<<dim3(3 * D_ / 32, D_ / 32), 256>>>(Wqkv, wqh, D_, 3 * D_);
    tcvt_h<<<dim3(D_ / 32, D_ / 32), 256>>>(Wout, woh, D_, D_);

    // 1) QKV projection + fused RMSNorm, fp16 output
    gemm_f16<3 * D_, D_, 1><<<dim3(3 * D_ / 128, (B_ * S_) / 128), 256, GEMM_SMEM>>>(
        xh, wqh, bqkv, (void*)qkvh, q_scale, k_scale);

    // 2) attention (fp16 mma, fp32 accumulate), fp16 output
    attn_f16<<<dim3(S_ / 128, B_ * H_), 256, ATT_SMEM>>>(qkvh, oh);

    // 3) output projection (fp32 output)
    gemm_f16<D_, D_, 0><<<dim3(D_ / 128, (B_ * S_) / 128), 256, GEMM_SMEM>>>(
        oh, woh, bout, (void*)out, q_scale, k_scale);
}

// round 11
// speedup vs baseline: 2.4882x; 1.1840x over previous
#include <cuda_runtime.h>
#include <cuda_fp16.h>
#include <math.h>

#define B_  2
#define S_  2048
#define D_  1024
#define H_  16
#define HD_ 64
#define EPS_ 1e-6f
// (1/sqrt(hd)) * log2(e), folded into q during fused rmsnorm
#define QFOLD 0.18033688011112042f

// Scratch (__device__ globals: allocation-free rule)
__device__ __half g_qkvh[B_ * S_ * 3 * D_];  // qkv fp16 (post-norm q,k)
__device__ __half g_oh [B_ * S_ * D_];       // attention out, fp16
__device__ __half g_xh [B_ * S_ * D_];       // x, fp16
__device__ __half g_wqh[3 * D_ * D_];        // Wqkv^T [3D][D], fp16
__device__ __half g_woh[D_ * D_];            // Wout^T [D][D],  fp16

// ---------------------------------------------------------------------------
__device__ __forceinline__ void mma_f16(float* c, const unsigned* a, const unsigned* b) {
    asm volatile(
        "mma.sync.aligned.m16n8k16.row.col.f32.f16.f16.f32 "
        "{%0,%1,%2,%3}, {%4,%5,%6,%7}, {%8,%9}, {%0,%1,%2,%3};"
        : "+f"(c[0]), "+f"(c[1]), "+f"(c[2]), "+f"(c[3])
        : "r"(a[0]), "r"(a[1]), "r"(a[2]), "r"(a[3]), "r"(b[0]), "r"(b[1]));
}
__device__ __forceinline__ void ldsm4(unsigned& r0, unsigned& r1, unsigned& r2,
                                      unsigned& r3, unsigned addr) {
    asm volatile("ldmatrix.sync.aligned.m8n8.x4.shared.b16 {%0,%1,%2,%3}, [%4];"
        : "=r"(r0), "=r"(r1), "=r"(r2), "=r"(r3) : "r"(addr));
}
__device__ __forceinline__ void ldsm4t(unsigned& r0, unsigned& r1, unsigned& r2,
                                       unsigned& r3, unsigned addr) {
    asm volatile("ldmatrix.sync.aligned.m8n8.x4.trans.shared.b16 {%0,%1,%2,%3}, [%4];"
        : "=r"(r0), "=r"(r1), "=r"(r2), "=r"(r3) : "r"(addr));
}
__device__ __forceinline__ unsigned sptr(const void* p) {
    return (unsigned)__cvta_generic_to_shared(p);
}
__device__ __forceinline__ void cpa16(unsigned dst, const void* src) {
    asm volatile("cp.async.cg.shared.global [%0], [%1], 16;" :: "r"(dst), "l"(src));
}
__device__ __forceinline__ void cp_commit() {
    asm volatile("cp.async.commit_group;");
}
template<int Np>
__device__ __forceinline__ void cp_wait() {
    asm volatile("cp.async.wait_group %0;" :: "n"(Np));
}
// pack two f32 into f16x2, then exp2 on both halves (one MUFU)
__device__ __forceinline__ unsigned ex2_pack(float lo, float hi) {
    __half2 h = __floats2half2_rn(lo, hi);
    unsigned s = *(unsigned*)&h, p;
    asm("ex2.approx.f16x2 %0, %1;" : "=r"(p) : "r"(s));
    return p;
}

// ---------------------------------------------------------------------------
// pre-pass: fp16 convert (+transpose for weights)
// ---------------------------------------------------------------------------
__global__ void cvt_h(const float* __restrict__ in, __half* __restrict__ out, int n4) {
    int i = blockIdx.x * blockDim.x + threadIdx.x;
    if (i < n4) {
        float4 v = ((const float4*)in)[i];
        __half2 h0 = __floats2half2_rn(v.x, v.y);
        __half2 h1 = __floats2half2_rn(v.z, v.w);
        ((uint2*)out)[i] = make_uint2(*(unsigned*)&h0, *(unsigned*)&h1);
    }
}
__global__ __launch_bounds__(256) void tcvt_h(
    const float* __restrict__ in, __half* __restrict__ out, int K, int N)
{
    __shared__ float t[32][33];
    int n0 = blockIdx.x * 32, k0 = blockIdx.y * 32;
    int tx = threadIdx.x & 31, ty = threadIdx.x >> 5;
#pragma unroll
    for (int r = ty; r < 32; r += 8)
        t[r][tx] = in[(size_t)(k0 + r) * N + n0 + tx];
    __syncthreads();
#pragma unroll
    for (int r = ty; r < 32; r += 8)
        out[(size_t)(n0 + r) * K + k0 + tx] = __float2half_rn(t[tx][r]);
}

// ---------------------------------------------------------------------------
// FP16 GEMM + bias (fp32 accumulate). MODE==1: fused per-head RMSNorm, fp16 out.
// (unchanged from round 9 — passing)
// ---------------------------------------------------------------------------
#define GHS 72
#define GSTG (128 * GHS * 2)
#define GEMM_SMEM (6 * GSTG)

template<int N, int K, int MODE>
__global__ __launch_bounds__(256, 2) void gemm_f16(
    const __half* __restrict__ A, const __half* __restrict__ Bt,
    const float* __restrict__ bias, void* __restrict__ Cv,
    const float* __restrict__ q_scale, const float* __restrict__ k_scale)
{
    extern __shared__ __half smh[];
    __half* As = smh;
    __half* Bs = smh + 3 * 128 * GHS;

    const int tid = threadIdx.x;
    const int lane = tid & 31;
    const int wid = tid >> 5;
    const int g = lane >> 2;
    const int q = lane & 3;
    const int wm = wid >> 1;
    const int wn = wid & 1;
    const int bxn = blockIdx.x * 128;
    const int bym = blockIdx.y * 128;

    const __half* asrc[4]; const __half* bsrc[4];
    unsigned adst[4], bdst[4];
#pragma unroll
    for (int i = 0; i < 4; ++i) {
        int idx = tid + 256 * i, r = idx >> 3, c = idx & 7;
        asrc[i] = A  + (size_t)(bym + r) * K + c * 8;
        bsrc[i] = Bt + (size_t)(bxn + r) * K + c * 8;
        adst[i] = sptr(As) + (r * GHS + c * 8) * 2;
        bdst[i] = sptr(Bs) + (r * GHS + c * 8) * 2;
    }

    const unsigned a_base = sptr(As) + ((wm * 32 + (lane & 15)) * GHS) * 2 + (lane >> 4) * 16;
    const unsigned b_base = sptr(Bs) + ((wn * 64 + (lane & 7) + ((lane >> 4) << 3)) * GHS) * 2
                          + ((lane >> 3) & 1) * 16;

    float acc[2][8][4];
#pragma unroll
    for (int mf = 0; mf < 2; ++mf)
#pragma unroll
        for (int nf = 0; nf < 8; ++nf)
#pragma unroll
            for (int e = 0; e < 4; ++e) acc[mf][nf][e] = 0.f;

    const int KT = K / 64;

#pragma unroll
    for (int i = 0; i < 4; ++i) { cpa16(adst[i], asrc[i]); cpa16(bdst[i], bsrc[i]); }
    cp_commit();
#pragma unroll
    for (int i = 0; i < 4; ++i) {
        cpa16(adst[i] + GSTG, asrc[i] + 64);
        cpa16(bdst[i] + GSTG, bsrc[i] + 64);
    }
    cp_commit();

    for (int kt = 0; kt < KT; ++kt) {
        if (kt + 1 < KT) cp_wait<1>(); else cp_wait<0>();
        __syncthreads();
        if (kt + 2 < KT) {
            const int koff = (kt + 2) * 64;
            const unsigned so = ((kt + 2) % 3) * GSTG;
#pragma unroll
            for (int i = 0; i < 4; ++i) {
                cpa16(adst[i] + so, asrc[i] + koff);
                cpa16(bdst[i] + so, bsrc[i] + koff);
            }
            cp_commit();
        }

        const unsigned a_s = a_base + (kt % 3) * GSTG;
        const unsigned b_s = b_base + (kt % 3) * GSTG;
#pragma unroll
        for (int ks = 0; ks < 4; ++ks) {
            unsigned a0[4], a1[4], bl[4][4];
            ldsm4(a0[0], a0[1], a0[2], a0[3], a_s + ks * 32);
            ldsm4(a1[0], a1[1], a1[2], a1[3], a_s + 16 * GHS * 2 + ks * 32);
#pragma unroll
            for (int t2 = 0; t2 < 4; ++t2)
                ldsm4(bl[t2][0], bl[t2][1], bl[t2][2], bl[t2][3],
                      b_s + t2 * 16 * GHS * 2 + ks * 32);
#pragma unroll
            for (int nf = 0; nf < 8; ++nf) {
                const unsigned* bf = &bl[nf >> 1][(nf & 1) * 2];
                mma_f16(acc[0][nf], a0, bf);
                mma_f16(acc[1][nf], a1, bf);
            }
        }
    }

    const bool donorm = (MODE == 1) && (bxn < 2048);
    const float* sc = (bxn < 1024) ? q_scale : k_scale;
    const float fold = (bxn < 1024) ? QFOLD : 1.0f;

#pragma unroll
    for (int mf = 0; mf < 2; ++mf) {
        int r0 = bym + wm * 32 + mf * 16 + g;
#pragma unroll
        for (int nf = 0; nf < 8; ++nf) {
            int col = bxn + wn * 64 + nf * 8 + 2 * q;
            float2 bs = *(const float2*)(bias + col);
            acc[mf][nf][0] += bs.x; acc[mf][nf][1] += bs.y;
            acc[mf][nf][2] += bs.x; acc[mf][nf][3] += bs.y;
        }
        if (donorm) {
#pragma unroll
            for (int rh = 0; rh < 2; ++rh) {
                const int e0 = rh * 2, e1 = e0 + 1;
                float ss = 0.f;
#pragma unroll
                for (int nf = 0; nf < 8; ++nf)
                    ss += acc[mf][nf][e0] * acc[mf][nf][e0]
                        + acc[mf][nf][e1] * acc[mf][nf][e1];
                ss += __shfl_xor_sync(0xffffffffu, ss, 1);
                ss += __shfl_xor_sync(0xffffffffu, ss, 2);
                float rr = rsqrtf(ss * (1.0f / HD_) + EPS_) * fold;
#pragma unroll
                for (int nf = 0; nf < 8; ++nf) {
                    float2 s2 = *(const float2*)(sc + nf * 8 + 2 * q);
                    acc[mf][nf][e0] *= rr * s2.x;
                    acc[mf][nf][e1] *= rr * s2.y;
                }
            }
        }
#pragma unroll
        for (int nf = 0; nf < 8; ++nf) {
            int col = bxn + wn * 64 + nf * 8 + 2 * q;
            if (MODE == 1) {
                __half* Ch = (__half*)Cv;
                *(__half2*)(Ch + (size_t)r0 * N + col) =
                    __floats2half2_rn(acc[mf][nf][0], acc[mf][nf][1]);
                *(__half2*)(Ch + (size_t)(r0 + 8) * N + col) =
                    __floats2half2_rn(acc[mf][nf][2], acc[mf][nf][3]);
            } else {
                float* Cf = (float*)Cv;
                *(float2*)(Cf + (size_t)r0 * N + col) =
                    make_float2(acc[mf][nf][0], acc[mf][nf][1]);
                *(float2*)(Cf + (size_t)(r0 + 8) * N + col) =
                    make_float2(acc[mf][nf][2], acc[mf][nf][3]);
            }
        }
    }
}

// ---------------------------------------------------------------------------
// FP16 flash attention, register-resident P (FA2 style), no online max:
// RMS-normed q,k bound |scores*QFOLD| <= 11.54, so p=exp2(s) <= 2980 < fp16 max.
// l computed exactly by a ones-column MMA (fp32). CTA: 256 thr, 128 queries,
// warp = 16 q-rows x 64 keys, cp.async double-buffered K/V.
// ---------------------------------------------------------------------------
#define HTS 72
#define OFK (128 * HTS)
#define OFV (OFK + 2 * 64 * HTS)
#define KVSTG (64 * HTS * 2)
#define ATT_SMEM ((OFV + 2 * 64 * HTS) * 2)   // 55296 B

__global__ __launch_bounds__(256, 2) void attn_f16(
    const __half* __restrict__ qkv, __half* __restrict__ o)
{
    extern __shared__ __half smh[];
    __half* Qh = smh;
    __half* Kh = smh + OFK;
    __half* Vh = smh + OFV;

    const int tid = threadIdx.x;
    const int lane = tid & 31;
    const int w = tid >> 5;
    const int g = lane >> 2;
    const int q = lane & 3;
    const int q0 = blockIdx.x * 128;
    const int bh = blockIdx.y;
    const int b = bh >> 4;
    const int h = bh & 15;

    const __half* base = qkv + (size_t)b * S_ * 3 * D_ + h * HD_;

    // K/V copy mapping: 2 x 16B chunks each (64 rows x 8 chunks)
    const __half* ksrc[2]; const __half* vsrc[2];
    unsigned kdst[2], vdst[2];
#pragma unroll
    for (int i = 0; i < 2; ++i) {
        int idx = tid + 256 * i, r = idx >> 3, c = idx & 7;
        ksrc[i] = base + (size_t)r * (3 * D_) + D_ + c * 8;
        vsrc[i] = base + (size_t)r * (3 * D_) + 2 * D_ + c * 8;
        kdst[i] = sptr(Kh) + (r * HTS + c * 8) * 2;
        vdst[i] = sptr(Vh) + (r * HTS + c * 8) * 2;
    }

    // prologue: Q (128 rows x 8 chunks) + K/V tile 0, one commit group
#pragma unroll
    for (int i = 0; i < 4; ++i) {
        int idx = tid + 256 * i, r = idx >> 3, c = idx & 7;
        cpa16(sptr(Qh) + (r * HTS + c * 8) * 2,
              base + (size_t)(q0 + r) * (3 * D_) + c * 8);
    }
#pragma unroll
    for (int i = 0; i < 2; ++i) { cpa16(kdst[i], ksrc[i]); cpa16(vdst[i], vsrc[i]); }
    cp_commit();

    const unsigned qbase = sptr(Qh) + ((w * 16 + (lane & 15)) * HTS) * 2 + (lane >> 4) * 16;
    const unsigned kbase = sptr(Kh)
        + (((lane & 7) + ((lane >> 4) << 3)) * HTS) * 2 + ((lane >> 3) & 1) * 16;
    const unsigned vbase = sptr(Vh)
        + (((lane & 7) + (((lane >> 3) & 1) << 3)) * HTS) * 2 + (lane >> 4) * 16;

    const unsigned ones2[2] = {0x3C003C00u, 0x3C003C00u};   // half2(1,1)

    unsigned qfrag[4][4];
    float lacc[4] = {0.f, 0.f, 0.f, 0.f};
    float acco[8][4];
#pragma unroll
    for (int nf = 0; nf < 8; ++nf)
#pragma unroll
        for (int e = 0; e < 4; ++e) acco[nf][e] = 0.f;

    const int T = S_ / 64;
    for (int t = 0; t < T; ++t) {
        cp_wait<0>();
        __syncthreads();
        if (t + 1 < T) {
            const size_t ko = (size_t)(t + 1) * 64 * (3 * D_);
            const unsigned so = ((t + 1) & 1) * KVSTG;
#pragma unroll
            for (int i = 0; i < 2; ++i) {
                cpa16(kdst[i] + so, ksrc[i] + ko);
                cpa16(vdst[i] + so, vsrc[i] + ko);
            }
            cp_commit();
        }
        if (t == 0) {   // hoist Q fragments to registers (constant across tiles)
#pragma unroll
            for (int ks = 0; ks < 4; ++ks)
                ldsm4(qfrag[ks][0], qfrag[ks][1], qfrag[ks][2], qfrag[ks][3],
                      qbase + ks * 32);
        }

        const unsigned k_s = kbase + (t & 1) * KVSTG;
        const unsigned v_s = vbase + (t & 1) * KVSTG;

        // S = Q K^T (accs includes QFOLD via pre-scaled q)
        float accs[8][4];
#pragma unroll
        for (int nf = 0; nf < 8; ++nf)
#pragma unroll
            for (int e = 0; e < 4; ++e) accs[nf][e] = 0.f;
#pragma unroll
        for (int ks = 0; ks < 4; ++ks) {
            unsigned bl[4][4];
#pragma unroll
            for (int t2 = 0; t2 < 4; ++t2)
                ldsm4(bl[t2][0], bl[t2][1], bl[t2][2], bl[t2][3],
                      k_s + t2 * 16 * HTS * 2 + ks * 32);
#pragma unroll
            for (int nf = 0; nf < 8; ++nf)
                mma_f16(accs[nf], qfrag[ks], &bl[nf >> 1][(nf & 1) * 2]);
        }

        // p = exp2(s), packed directly as PV A-fragments (registers only)
        unsigned pa[4][4];
#pragma unroll
        for (int j = 0; j < 4; ++j) {
            pa[j][0] = ex2_pack(accs[2 * j][0],     accs[2 * j][1]);
            pa[j][1] = ex2_pack(accs[2 * j][2],     accs[2 * j][3]);
            pa[j][2] = ex2_pack(accs[2 * j + 1][0], accs[2 * j + 1][1]);
            pa[j][3] = ex2_pack(accs[2 * j + 1][2], accs[2 * j + 1][3]);
        }

        // O += P V ; l += P * ones (exact fp32 row sums)
#pragma unroll
        for (int ks = 0; ks < 4; ++ks) {
            unsigned bl[4][4];
#pragma unroll
            for (int t2 = 0; t2 < 4; ++t2)
                ldsm4t(bl[t2][0], bl[t2][1], bl[t2][2], bl[t2][3],
                       v_s + ks * 16 * HTS * 2 + t2 * 32);
#pragma unroll
            for (int nf = 0; nf < 8; ++nf)
                mma_f16(acco[nf], pa[ks], &bl[nf >> 1][(nf & 1) * 2]);
            mma_f16(lacc, pa[ks], ones2);
        }
    }

    // epilogue: O / l, store fp16
#pragma unroll
    for (int rh = 0; rh < 2; ++rh) {
        float inv = 1.0f / lacc[rh * 2];     // rows g (rh=0) / g+8 (rh=1)
        int row = q0 + w * 16 + g + rh * 8;
        __half* orow = o + (size_t)(b * S_ + row) * D_ + h * HD_;
        const int e0 = rh * 2, e1 = e0 + 1;
#pragma unroll
        for (int nf = 0; nf < 8; ++nf)
            *(__half2*)(orow + nf * 8 + 2 * q) =
                __floats2half2_rn(acco[nf][e0] * inv, acco[nf][e1] * inv);
    }
}

// ---------------------------------------------------------------------------
extern "C" void kernel_launch(void* const* d_in, const int* in_sizes, int n_in,
                              void* d_out, int out_size)
{
    const float* x       = (const float*)d_in[0];
    const float* Wqkv    = (const float*)d_in[1];
    const float* bqkv    = (const float*)d_in[2];
    const float* Wout    = (const float*)d_in[3];
    const float* bout    = (const float*)d_in[4];
    const float* q_scale = (const float*)d_in[5];
    const float* k_scale = (const float*)d_in[6];
    float* out = (float*)d_out;

    __half* qkvh; cudaGetSymbolAddress((void**)&qkvh, g_qkvh);
    __half* oh;   cudaGetSymbolAddress((void**)&oh,   g_oh);
    __half* xh;   cudaGetSymbolAddress((void**)&xh,   g_xh);
    __half* wqh;  cudaGetSymbolAddress((void**)&wqh,  g_wqh);
    __half* woh;  cudaGetSymbolAddress((void**)&woh,  g_woh);

    cudaFuncSetAttribute((const void*)gemm_f16<3 * D_, D_, 1>,
                         cudaFuncAttributeMaxDynamicSharedMemorySize, GEMM_SMEM);
    cudaFuncSetAttribute((const void*)gemm_f16<D_, D_, 0>,
                         cudaFuncAttributeMaxDynamicSharedMemorySize, GEMM_SMEM);
    cudaFuncSetAttribute((const void*)attn_f16,
                         cudaFuncAttributeMaxDynamicSharedMemorySize, ATT_SMEM);

    // 0) pre-convert x + weights to fp16 (weights transposed)
    cvt_h<<<(B_ * S_ * D_ / 4 + 255) / 256, 256>>>(x, xh, B_ * S_ * D_ / 4);
    tcvt_h<<<dim3(3 * D_ / 32, D_ / 32), 256>>>(Wqkv, wqh, D_, 3 * D_);
    tcvt_h<<<dim3(D_ / 32, D_ / 32), 256>>>(Wout, woh, D_, D_);

    // 1) QKV projection + fused RMSNorm, fp16 output
    gemm_f16<3 * D_, D_, 1><<<dim3(3 * D_ / 128, (B_ * S_) / 128), 256, GEMM_SMEM>>>(
        xh, wqh, bqkv, (void*)qkvh, q_scale, k_scale);

    // 2) attention (register-resident P, no-max softmax), fp16 output
    attn_f16<<<dim3(S_ / 128, B_ * H_), 256, ATT_SMEM>>>(qkvh, oh);

    // 3) output projection (fp32 output)
    gemm_f16<D_, D_, 0><<<dim3(D_ / 128, (B_ * S_) / 128), 256, GEMM_SMEM>>>(
        oh, woh, bout, (void*)out, q_scale, k_scale);
}

// round 12
// speedup vs baseline: 2.6580x; 1.0682x over previous
#include <cuda_runtime.h>
#include <cuda_fp16.h>
#include <math.h>

#define B_  2
#define S_  2048
#define D_  1024
#define H_  16
#define HD_ 64
#define EPS_ 1e-6f
// (1/sqrt(hd)) * log2(e), folded into q during fused rmsnorm
#define QFOLD 0.18033688011112042f

// Scratch (__device__ globals: allocation-free rule)
__device__ __half g_qkvh[B_ * S_ * 3 * D_];  // qkv fp16 (post-norm q,k)
__device__ __half g_oh [B_ * S_ * D_];       // attention out, fp16
__device__ __half g_xh [B_ * S_ * D_];       // x, fp16
__device__ __half g_wqh[3 * D_ * D_];        // Wqkv^T [3D][D], fp16
__device__ __half g_woh[D_ * D_];            // Wout^T [D][D],  fp16

// ---------------------------------------------------------------------------
__device__ __forceinline__ void mma_f16(float* c, const unsigned* a, const unsigned* b) {
    asm volatile(
        "mma.sync.aligned.m16n8k16.row.col.f32.f16.f16.f32 "
        "{%0,%1,%2,%3}, {%4,%5,%6,%7}, {%8,%9}, {%0,%1,%2,%3};"
        : "+f"(c[0]), "+f"(c[1]), "+f"(c[2]), "+f"(c[3])
        : "r"(a[0]), "r"(a[1]), "r"(a[2]), "r"(a[3]), "r"(b[0]), "r"(b[1]));
}
__device__ __forceinline__ void ldsm4(unsigned& r0, unsigned& r1, unsigned& r2,
                                      unsigned& r3, unsigned addr) {
    asm volatile("ldmatrix.sync.aligned.m8n8.x4.shared.b16 {%0,%1,%2,%3}, [%4];"
        : "=r"(r0), "=r"(r1), "=r"(r2), "=r"(r3) : "r"(addr));
}
__device__ __forceinline__ void ldsm4t(unsigned& r0, unsigned& r1, unsigned& r2,
                                       unsigned& r3, unsigned addr) {
    asm volatile("ldmatrix.sync.aligned.m8n8.x4.trans.shared.b16 {%0,%1,%2,%3}, [%4];"
        : "=r"(r0), "=r"(r1), "=r"(r2), "=r"(r3) : "r"(addr));
}
__device__ __forceinline__ unsigned sptr(const void* p) {
    return (unsigned)__cvta_generic_to_shared(p);
}
__device__ __forceinline__ void cpa16(unsigned dst, const void* src) {
    asm volatile("cp.async.cg.shared.global [%0], [%1], 16;" :: "r"(dst), "l"(src));
}
__device__ __forceinline__ void cp_commit() {
    asm volatile("cp.async.commit_group;");
}
template<int Np>
__device__ __forceinline__ void cp_wait() {
    asm volatile("cp.async.wait_group %0;" :: "n"(Np));
}
// pack two f32 into f16x2, then exp2 on both halves (one MUFU)
__device__ __forceinline__ unsigned ex2_pack(float lo, float hi) {
    __half2 h = __floats2half2_rn(lo, hi);
    unsigned s = *(unsigned*)&h, p;
    asm("ex2.approx.f16x2 %0, %1;" : "=r"(p) : "r"(s));
    return p;
}

// ---------------------------------------------------------------------------
// pre-pass: fp16 convert (+transpose for weights)
// ---------------------------------------------------------------------------
__global__ void cvt_h(const float* __restrict__ in, __half* __restrict__ out, int n4) {
    int i = blockIdx.x * blockDim.x + threadIdx.x;
    if (i < n4) {
        float4 v = ((const float4*)in)[i];
        __half2 h0 = __floats2half2_rn(v.x, v.y);
        __half2 h1 = __floats2half2_rn(v.z, v.w);
        ((uint2*)out)[i] = make_uint2(*(unsigned*)&h0, *(unsigned*)&h1);
    }
}
__global__ __launch_bounds__(256) void tcvt_h(
    const float* __restrict__ in, __half* __restrict__ out, int K, int N)
{
    __shared__ float t[32][33];
    int n0 = blockIdx.x * 32, k0 = blockIdx.y * 32;
    int tx = threadIdx.x & 31, ty = threadIdx.x >> 5;
#pragma unroll
    for (int r = ty; r < 32; r += 8)
        t[r][tx] = in[(size_t)(k0 + r) * N + n0 + tx];
    __syncthreads();
#pragma unroll
    for (int r = ty; r < 32; r += 8)
        out[(size_t)(n0 + r) * K + k0 + tx] = __float2half_rn(t[tx][r]);
}

// ---------------------------------------------------------------------------
// FP16 GEMM + bias (fp32 accumulate). MODE==1: fused per-head RMSNorm, fp16 out.
// C[M,N] = A[M,K] @ Bt^T + bias ; Bt is [N][K] (pre-transposed, fp16).
// 128x128x64 tile, 8 warps, warp 32x64, m16n8k16, 3-stage cp.async.
// Single base pointer per operand; all chunk/stage offsets compile-time.
// ---------------------------------------------------------------------------
#define GHS 72
#define GSTG (128 * GHS * 2)
#define GEMM_SMEM (6 * GSTG)

template<int N, int K, int MODE>
__global__ __launch_bounds__(256, 2) void gemm_f16(
    const __half* __restrict__ A, const __half* __restrict__ Bt,
    const float* __restrict__ bias, void* __restrict__ Cv,
    const float* __restrict__ q_scale, const float* __restrict__ k_scale)
{
    extern __shared__ __half smh[];
    __half* As = smh;
    __half* Bs = smh + 3 * 128 * GHS;

    const int tid = threadIdx.x;
    const int lane = tid & 31;
    const int wid = tid >> 5;
    const int g = lane >> 2;
    const int q = lane & 3;
    const int wm = wid >> 1;
    const int wn = wid & 1;
    const int bxn = blockIdx.x * 128;
    const int bym = blockIdx.y * 128;

    // single-base copy mapping: chunk i => row (tid>>3)+32i, col (tid&7)*8
    const int cr = tid >> 3, cc = (tid & 7) * 8;
    const __half* asrc = A  + (size_t)(bym + cr) * K + cc;
    const __half* bsrc = Bt + (size_t)(bxn + cr) * K + cc;
    const unsigned adst = sptr(As) + (cr * GHS + cc) * 2;
    const unsigned bdst = sptr(Bs) + (cr * GHS + cc) * 2;

    const unsigned a_base = sptr(As) + ((wm * 32 + (lane & 15)) * GHS) * 2 + (lane >> 4) * 16;
    const unsigned b_base = sptr(Bs) + ((wn * 64 + (lane & 7) + ((lane >> 4) << 3)) * GHS) * 2
                          + ((lane >> 3) & 1) * 16;

    float acc[2][8][4];
#pragma unroll
    for (int mf = 0; mf < 2; ++mf)
#pragma unroll
        for (int nf = 0; nf < 8; ++nf)
#pragma unroll
            for (int e = 0; e < 4; ++e) acc[mf][nf][e] = 0.f;

    constexpr int KT = K / 64;

    // prologue: stages 0 and 1
#pragma unroll
    for (int i = 0; i < 4; ++i) {
        cpa16(adst + i * (32 * GHS * 2), asrc + i * (size_t)(32 * K));
        cpa16(bdst + i * (32 * GHS * 2), bsrc + i * (size_t)(32 * K));
    }
    cp_commit();
#pragma unroll
    for (int i = 0; i < 4; ++i) {
        cpa16(adst + i * (32 * GHS * 2) + GSTG, asrc + i * (size_t)(32 * K) + 64);
        cpa16(bdst + i * (32 * GHS * 2) + GSTG, bsrc + i * (size_t)(32 * K) + 64);
    }
    cp_commit();

#pragma unroll
    for (int kt = 0; kt < KT; ++kt) {
        if (kt + 1 < KT) cp_wait<1>(); else cp_wait<0>();
        __syncthreads();
        if (kt + 2 < KT) {
            constexpr int dummy = 0; (void)dummy;
            const int koff = (kt + 2) * 64;                  // compile-time (unrolled)
            const unsigned so = ((kt + 2) % 3) * GSTG;       // compile-time (unrolled)
#pragma unroll
            for (int i = 0; i < 4; ++i) {
                cpa16(adst + i * (32 * GHS * 2) + so, asrc + i * (size_t)(32 * K) + koff);
                cpa16(bdst + i * (32 * GHS * 2) + so, bsrc + i * (size_t)(32 * K) + koff);
            }
            cp_commit();
        }

        const unsigned a_s = a_base + (kt % 3) * GSTG;       // compile-time (unrolled)
        const unsigned b_s = b_base + (kt % 3) * GSTG;
#pragma unroll
        for (int ks = 0; ks < 4; ++ks) {
            unsigned a0[4], a1[4], bl[4][4];
            ldsm4(a0[0], a0[1], a0[2], a0[3], a_s + ks * 32);
            ldsm4(a1[0], a1[1], a1[2], a1[3], a_s + 16 * GHS * 2 + ks * 32);
#pragma unroll
            for (int t2 = 0; t2 < 4; ++t2)
                ldsm4(bl[t2][0], bl[t2][1], bl[t2][2], bl[t2][3],
                      b_s + t2 * 16 * GHS * 2 + ks * 32);
#pragma unroll
            for (int nf = 0; nf < 8; ++nf) {
                const unsigned* bf = &bl[nf >> 1][(nf & 1) * 2];
                mma_f16(acc[0][nf], a0, bf);
                mma_f16(acc[1][nf], a1, bf);
            }
        }
    }

    const bool donorm = (MODE == 1) && (bxn < 2048);
    const float* sc = (bxn < 1024) ? q_scale : k_scale;
    const float fold = (bxn < 1024) ? QFOLD : 1.0f;

#pragma unroll
    for (int mf = 0; mf < 2; ++mf) {
        int r0 = bym + wm * 32 + mf * 16 + g;
#pragma unroll
        for (int nf = 0; nf < 8; ++nf) {
            int col = bxn + wn * 64 + nf * 8 + 2 * q;
            float2 bs = *(const float2*)(bias + col);
            acc[mf][nf][0] += bs.x; acc[mf][nf][1] += bs.y;
            acc[mf][nf][2] += bs.x; acc[mf][nf][3] += bs.y;
        }
        if (donorm) {
#pragma unroll
            for (int rh = 0; rh < 2; ++rh) {
                const int e0 = rh * 2, e1 = e0 + 1;
                float ss = 0.f;
#pragma unroll
                for (int nf = 0; nf < 8; ++nf)
                    ss += acc[mf][nf][e0] * acc[mf][nf][e0]
                        + acc[mf][nf][e1] * acc[mf][nf][e1];
                ss += __shfl_xor_sync(0xffffffffu, ss, 1);
                ss += __shfl_xor_sync(0xffffffffu, ss, 2);
                float rr = rsqrtf(ss * (1.0f / HD_) + EPS_) * fold;
#pragma unroll
                for (int nf = 0; nf < 8; ++nf) {
                    float2 s2 = *(const float2*)(sc + nf * 8 + 2 * q);
                    acc[mf][nf][e0] *= rr * s2.x;
                    acc[mf][nf][e1] *= rr * s2.y;
                }
            }
        }
#pragma unroll
        for (int nf = 0; nf < 8; ++nf) {
            int col = bxn + wn * 64 + nf * 8 + 2 * q;
            if (MODE == 1) {
                __half* Ch = (__half*)Cv;
                *(__half2*)(Ch + (size_t)r0 * N + col) =
                    __floats2half2_rn(acc[mf][nf][0], acc[mf][nf][1]);
                *(__half2*)(Ch + (size_t)(r0 + 8) * N + col) =
                    __floats2half2_rn(acc[mf][nf][2], acc[mf][nf][3]);
            } else {
                float* Cf = (float*)Cv;
                *(float2*)(Cf + (size_t)r0 * N + col) =
                    make_float2(acc[mf][nf][0], acc[mf][nf][1]);
                *(float2*)(Cf + (size_t)(r0 + 8) * N + col) =
                    make_float2(acc[mf][nf][2], acc[mf][nf][3]);
            }
        }
    }
}

// ---------------------------------------------------------------------------
// FP16 flash attention, register-resident P, no online max (bounded scores),
// l via ones-column MMA. CTA: 256 thr, 128 queries, warp = 16q x 64keys,
// cp.async double-buffered K/V. Single-base copy pointers; t-loop unroll 2.
// ---------------------------------------------------------------------------
#define HTS 72
#define OFK (128 * HTS)
#define OFV (OFK + 2 * 64 * HTS)
#define KVSTG (64 * HTS * 2)
#define ATT_SMEM ((OFV + 2 * 64 * HTS) * 2)   // 55296 B

__global__ __launch_bounds__(256, 2) void attn_f16(
    const __half* __restrict__ qkv, __half* __restrict__ o)
{
    extern __shared__ __half smh[];
    __half* Qh = smh;
    __half* Kh = smh + OFK;
    __half* Vh = smh + OFV;

    const int tid = threadIdx.x;
    const int lane = tid & 31;
    const int w = tid >> 5;
    const int g = lane >> 2;
    const int q = lane & 3;
    const int q0 = blockIdx.x * 128;
    const int bh = blockIdx.y;
    const int b = bh >> 4;
    const int h = bh & 15;

    const __half* base = qkv + (size_t)b * S_ * 3 * D_ + h * HD_;

    // single-base copy mapping: chunk i => row (tid>>3)+32i, col (tid&7)*8
    const int cr = tid >> 3, cc = (tid & 7) * 8;
    const __half* ksrc = base + (size_t)cr * (3 * D_) + D_ + cc;
    const __half* vsrc = base + (size_t)cr * (3 * D_) + 2 * D_ + cc;
    const unsigned kdst = sptr(Kh) + (cr * HTS + cc) * 2;
    const unsigned vdst = sptr(Vh) + (cr * HTS + cc) * 2;

    // prologue: Q (128 rows x 8 chunks; 4 chunks/thread) + K/V tile 0
#pragma unroll
    for (int i = 0; i < 4; ++i)
        cpa16(sptr(Qh) + (cr * HTS + cc) * 2 + i * (32 * HTS * 2),
              base + (size_t)(q0 + cr) * (3 * D_) + cc + (size_t)i * (32 * 3 * D_));
#pragma unroll
    for (int i = 0; i < 2; ++i) {
        cpa16(kdst + i * (32 * HTS * 2), ksrc + (size_t)i * (32 * 3 * D_));
        cpa16(vdst + i * (32 * HTS * 2), vsrc + (size_t)i * (32 * 3 * D_));
    }
    cp_commit();

    const unsigned qbase = sptr(Qh) + ((w * 16 + (lane & 15)) * HTS) * 2 + (lane >> 4) * 16;
    const unsigned kbase = sptr(Kh)
        + (((lane & 7) + ((lane >> 4) << 3)) * HTS) * 2 + ((lane >> 3) & 1) * 16;
    const unsigned vbase = sptr(Vh)
        + (((lane & 7) + (((lane >> 3) & 1) << 3)) * HTS) * 2 + (lane >> 4) * 16;

    const unsigned ones2[2] = {0x3C003C00u, 0x3C003C00u};   // half2(1,1)

    unsigned qfrag[4][4];
    float lacc[4] = {0.f, 0.f, 0.f, 0.f};
    float acco[8][4];
#pragma unroll
    for (int nf = 0; nf < 8; ++nf)
#pragma unroll
        for (int e = 0; e < 4; ++e) acco[nf][e] = 0.f;

    const int T = S_ / 64;
#pragma unroll 2
    for (int t = 0; t < T; ++t) {
        cp_wait<0>();
        __syncthreads();
        if (t + 1 < T) {
            const size_t ko = (size_t)(t + 1) * 64 * (3 * D_);
            const unsigned so = ((t + 1) & 1) * KVSTG;   // compile-time (unroll 2)
#pragma unroll
            for (int i = 0; i < 2; ++i) {
                cpa16(kdst + i * (32 * HTS * 2) + so, ksrc + ko + (size_t)i * (32 * 3 * D_));
                cpa16(vdst + i * (32 * HTS * 2) + so, vsrc + ko + (size_t)i * (32 * 3 * D_));
            }
            cp_commit();
        }
        if (t == 0) {   // hoist Q fragments (constant across tiles)
#pragma unroll
            for (int ks = 0; ks < 4; ++ks)
                ldsm4(qfrag[ks][0], qfrag[ks][1], qfrag[ks][2], qfrag[ks][3],
                      qbase + ks * 32);
        }

        const unsigned k_s = kbase + (t & 1) * KVSTG;
        const unsigned v_s = vbase + (t & 1) * KVSTG;

        // S = Q K^T
        float accs[8][4];
#pragma unroll
        for (int nf = 0; nf < 8; ++nf)
#pragma unroll
            for (int e = 0; e < 4; ++e) accs[nf][e] = 0.f;
#pragma unroll
        for (int ks = 0; ks < 4; ++ks) {
            unsigned bl[4][4];
#pragma unroll
            for (int t2 = 0; t2 < 4; ++t2)
                ldsm4(bl[t2][0], bl[t2][1], bl[t2][2], bl[t2][3],
                      k_s + t2 * 16 * HTS * 2 + ks * 32);
#pragma unroll
            for (int nf = 0; nf < 8; ++nf)
                mma_f16(accs[nf], qfrag[ks], &bl[nf >> 1][(nf & 1) * 2]);
        }

        // p = exp2(s) packed directly as PV A-fragments
        unsigned pa[4][4];
#pragma unroll
        for (int j = 0; j < 4; ++j) {
            pa[j][0] = ex2_pack(accs[2 * j][0],     accs[2 * j][1]);
            pa[j][1] = ex2_pack(accs[2 * j][2],     accs[2 * j][3]);
            pa[j][2] = ex2_pack(accs[2 * j + 1][0], accs[2 * j + 1][1]);
            pa[j][3] = ex2_pack(accs[2 * j + 1][2], accs[2 * j + 1][3]);
        }

        // O += P V ; l += P * ones
#pragma unroll
        for (int ks = 0; ks < 4; ++ks) {
            unsigned bl[4][4];
#pragma unroll
            for (int t2 = 0; t2 < 4; ++t2)
                ldsm4t(bl[t2][0], bl[t2][1], bl[t2][2], bl[t2][3],
                       v_s + ks * 16 * HTS * 2 + t2 * 32);
#pragma unroll
            for (int nf = 0; nf < 8; ++nf)
                mma_f16(acco[nf], pa[ks], &bl[nf >> 1][(nf & 1) * 2]);
            mma_f16(lacc, pa[ks], ones2);
        }
    }

    // epilogue: O / l, store fp16
#pragma unroll
    for (int rh = 0; rh < 2; ++rh) {
        float inv = 1.0f / lacc[rh * 2];
        int row = q0 + w * 16 + g + rh * 8;
        __half* orow = o + (size_t)(b * S_ + row) * D_ + h * HD_;
        const int e0 = rh * 2, e1 = e0 + 1;
#pragma unroll
        for (int nf = 0; nf < 8; ++nf)
            *(__half2*)(orow + nf * 8 + 2 * q) =
                __floats2half2_rn(acco[nf][e0] * inv, acco[nf][e1] * inv);
    }
}

// ---------------------------------------------------------------------------
extern "C" void kernel_launch(void* const* d_in, const int* in_sizes, int n_in,
                              void* d_out, int out_size)
{
    const float* x       = (const float*)d_in[0];
    const float* Wqkv    = (const float*)d_in[1];
    const float* bqkv    = (const float*)d_in[2];
    const float* Wout    = (const float*)d_in[3];
    const float* bout    = (const float*)d_in[4];
    const float* q_scale = (const float*)d_in[5];
    const float* k_scale = (const float*)d_in[6];
    float* out = (float*)d_out;

    __half* qkvh; cudaGetSymbolAddress((void**)&qkvh, g_qkvh);
    __half* oh;   cudaGetSymbolAddress((void**)&oh,   g_oh);
    __half* xh;   cudaGetSymbolAddress((void**)&xh,   g_xh);
    __half* wqh;  cudaGetSymbolAddress((void**)&wqh,  g_wqh);
    __half* woh;  cudaGetSymbolAddress((void**)&woh,  g_woh);

    cudaFuncSetAttribute((const void*)gemm_f16<3 * D_, D_, 1>,
                         cudaFuncAttributeMaxDynamicSharedMemorySize, GEMM_SMEM);
    cudaFuncSetAttribute((const void*)gemm_f16<D_, D_, 0>,
                         cudaFuncAttributeMaxDynamicSharedMemorySize, GEMM_SMEM);
    cudaFuncSetAttribute((const void*)attn_f16,
                         cudaFuncAttributeMaxDynamicSharedMemorySize, ATT_SMEM);

    // 0) pre-convert x + weights to fp16 (weights transposed)
    cvt_h<<<(B_ * S_ * D_ / 4 + 255) / 256, 256>>>(x, xh, B_ * S_ * D_ / 4);
    tcvt_h<<<dim3(3 * D_ / 32, D_ / 32), 256>>>(Wqkv, wqh, D_, 3 * D_);
    tcvt_h<<<dim3(D_ / 32, D_ / 32), 256>>>(Wout, woh, D_, D_);

    // 1) QKV projection + fused RMSNorm, fp16 output
    gemm_f16<3 * D_, D_, 1><<<dim3(3 * D_ / 128, (B_ * S_) / 128), 256, GEMM_SMEM>>>(
        xh, wqh, bqkv, (void*)qkvh, q_scale, k_scale);

    // 2) attention (register-resident P, no-max softmax), fp16 output
    attn_f16<<<dim3(S_ / 128, B_ * H_), 256, ATT_SMEM>>>(qkvh, oh);

    // 3) output projection (fp32 output)
    gemm_f16<D_, D_, 0><<<dim3(D_ / 128, (B_ * S_) / 128), 256, GEMM_SMEM>>>(
        oh, woh, bout, (void*)out, q_scale, k_scale);
}

// round 13
// speedup vs baseline: 2.8017x; 1.0541x over previous
#include <cuda_runtime.h>
#include <cuda_fp16.h>
#include <math.h>

#define B_  2
#define S_  2048
#define D_  1024
#define H_  16
#define HD_ 64
#define EPS_ 1e-6f
// (1/sqrt(hd)) * log2(e), folded into q during fused rmsnorm
#define QFOLD 0.18033688011112042f

// Scratch (__device__ globals: allocation-free rule)
__device__ __half g_qkvh[B_ * S_ * 3 * D_];  // qkv fp16 (post-norm q,k)
__device__ __half g_oh [B_ * S_ * D_];       // attention out, fp16
__device__ __half g_xh [B_ * S_ * D_];       // x, fp16
__device__ __half g_wqh[3 * D_ * D_];        // Wqkv^T [3D][D], fp16
__device__ __half g_woh[D_ * D_];            // Wout^T [D][D],  fp16

// ---------------------------------------------------------------------------
__device__ __forceinline__ void mma_f16(float* c, const unsigned* a, const unsigned* b) {
    asm volatile(
        "mma.sync.aligned.m16n8k16.row.col.f32.f16.f16.f32 "
        "{%0,%1,%2,%3}, {%4,%5,%6,%7}, {%8,%9}, {%0,%1,%2,%3};"
        : "+f"(c[0]), "+f"(c[1]), "+f"(c[2]), "+f"(c[3])
        : "r"(a[0]), "r"(a[1]), "r"(a[2]), "r"(a[3]), "r"(b[0]), "r"(b[1]));
}
__device__ __forceinline__ void ldsm4(unsigned& r0, unsigned& r1, unsigned& r2,
                                      unsigned& r3, unsigned addr) {
    asm volatile("ldmatrix.sync.aligned.m8n8.x4.shared.b16 {%0,%1,%2,%3}, [%4];"
        : "=r"(r0), "=r"(r1), "=r"(r2), "=r"(r3) : "r"(addr));
}
__device__ __forceinline__ void ldsm4t(unsigned& r0, unsigned& r1, unsigned& r2,
                                       unsigned& r3, unsigned addr) {
    asm volatile("ldmatrix.sync.aligned.m8n8.x4.trans.shared.b16 {%0,%1,%2,%3}, [%4];"
        : "=r"(r0), "=r"(r1), "=r"(r2), "=r"(r3) : "r"(addr));
}
__device__ __forceinline__ unsigned sptr(const void* p) {
    return (unsigned)__cvta_generic_to_shared(p);
}
__device__ __forceinline__ void cpa16(unsigned dst, const void* src) {
    asm volatile("cp.async.cg.shared.global [%0], [%1], 16;" :: "r"(dst), "l"(src));
}
__device__ __forceinline__ void cp_commit() {
    asm volatile("cp.async.commit_group;");
}
template<int Np>
__device__ __forceinline__ void cp_wait() {
    asm volatile("cp.async.wait_group %0;" :: "n"(Np));
}
// pack two f32 into f16x2, then exp2 on both halves (one MUFU)
__device__ __forceinline__ unsigned ex2_pack(float lo, float hi) {
    __half2 h = __floats2half2_rn(lo, hi);
    unsigned s = *(unsigned*)&h, p;
    asm("ex2.approx.f16x2 %0, %1;" : "=r"(p) : "r"(s));
    return p;
}

// ---------------------------------------------------------------------------
// pre-pass: fp16 convert (+transpose for weights)
// ---------------------------------------------------------------------------
__global__ void cvt_h(const float* __restrict__ in, __half* __restrict__ out, int n4) {
    int i = blockIdx.x * blockDim.x + threadIdx.x;
    if (i < n4) {
        float4 v = ((const float4*)in)[i];
        __half2 h0 = __floats2half2_rn(v.x, v.y);
        __half2 h1 = __floats2half2_rn(v.z, v.w);
        ((uint2*)out)[i] = make_uint2(*(unsigned*)&h0, *(unsigned*)&h1);
    }
}
__global__ __launch_bounds__(256) void tcvt_h(
    const float* __restrict__ in, __half* __restrict__ out, int K, int N)
{
    __shared__ float t[32][33];
    int n0 = blockIdx.x * 32, k0 = blockIdx.y * 32;
    int tx = threadIdx.x & 31, ty = threadIdx.x >> 5;
#pragma unroll
    for (int r = ty; r < 32; r += 8)
        t[r][tx] = in[(size_t)(k0 + r) * N + n0 + tx];
    __syncthreads();
#pragma unroll
    for (int r = ty; r < 32; r += 8)
        out[(size_t)(n0 + r) * K + k0 + tx] = __float2half_rn(t[tx][r]);
}

// ---------------------------------------------------------------------------
// FP16 GEMM + bias (fp32 accumulate). MODE==1: fused per-head RMSNorm, fp16 out.
// (unchanged from round 12 — passing, tensor 55%)
// ---------------------------------------------------------------------------
#define GHS 72
#define GSTG (128 * GHS * 2)
#define GEMM_SMEM (6 * GSTG)

template<int N, int K, int MODE>
__global__ __launch_bounds__(256, 2) void gemm_f16(
    const __half* __restrict__ A, const __half* __restrict__ Bt,
    const float* __restrict__ bias, void* __restrict__ Cv,
    const float* __restrict__ q_scale, const float* __restrict__ k_scale)
{
    extern __shared__ __half smh[];
    __half* As = smh;
    __half* Bs = smh + 3 * 128 * GHS;

    const int tid = threadIdx.x;
    const int lane = tid & 31;
    const int wid = tid >> 5;
    const int g = lane >> 2;
    const int q = lane & 3;
    const int wm = wid >> 1;
    const int wn = wid & 1;
    const int bxn = blockIdx.x * 128;
    const int bym = blockIdx.y * 128;

    const int cr = tid >> 3, cc = (tid & 7) * 8;
    const __half* asrc = A  + (size_t)(bym + cr) * K + cc;
    const __half* bsrc = Bt + (size_t)(bxn + cr) * K + cc;
    const unsigned adst = sptr(As) + (cr * GHS + cc) * 2;
    const unsigned bdst = sptr(Bs) + (cr * GHS + cc) * 2;

    const unsigned a_base = sptr(As) + ((wm * 32 + (lane & 15)) * GHS) * 2 + (lane >> 4) * 16;
    const unsigned b_base = sptr(Bs) + ((wn * 64 + (lane & 7) + ((lane >> 4) << 3)) * GHS) * 2
                          + ((lane >> 3) & 1) * 16;

    float acc[2][8][4];
#pragma unroll
    for (int mf = 0; mf < 2; ++mf)
#pragma unroll
        for (int nf = 0; nf < 8; ++nf)
#pragma unroll
            for (int e = 0; e < 4; ++e) acc[mf][nf][e] = 0.f;

    constexpr int KT = K / 64;

#pragma unroll
    for (int i = 0; i < 4; ++i) {
        cpa16(adst + i * (32 * GHS * 2), asrc + i * (size_t)(32 * K));
        cpa16(bdst + i * (32 * GHS * 2), bsrc + i * (size_t)(32 * K));
    }
    cp_commit();
#pragma unroll
    for (int i = 0; i < 4; ++i) {
        cpa16(adst + i * (32 * GHS * 2) + GSTG, asrc + i * (size_t)(32 * K) + 64);
        cpa16(bdst + i * (32 * GHS * 2) + GSTG, bsrc + i * (size_t)(32 * K) + 64);
    }
    cp_commit();

#pragma unroll
    for (int kt = 0; kt < KT; ++kt) {
        if (kt + 1 < KT) cp_wait<1>(); else cp_wait<0>();
        __syncthreads();
        if (kt + 2 < KT) {
            const int koff = (kt + 2) * 64;
            const unsigned so = ((kt + 2) % 3) * GSTG;
#pragma unroll
            for (int i = 0; i < 4; ++i) {
                cpa16(adst + i * (32 * GHS * 2) + so, asrc + i * (size_t)(32 * K) + koff);
                cpa16(bdst + i * (32 * GHS * 2) + so, bsrc + i * (size_t)(32 * K) + koff);
            }
            cp_commit();
        }

        const unsigned a_s = a_base + (kt % 3) * GSTG;
        const unsigned b_s = b_base + (kt % 3) * GSTG;
#pragma unroll
        for (int ks = 0; ks < 4; ++ks) {
            unsigned a0[4], a1[4], bl[4][4];
            ldsm4(a0[0], a0[1], a0[2], a0[3], a_s + ks * 32);
            ldsm4(a1[0], a1[1], a1[2], a1[3], a_s + 16 * GHS * 2 + ks * 32);
#pragma unroll
            for (int t2 = 0; t2 < 4; ++t2)
                ldsm4(bl[t2][0], bl[t2][1], bl[t2][2], bl[t2][3],
                      b_s + t2 * 16 * GHS * 2 + ks * 32);
#pragma unroll
            for (int nf = 0; nf < 8; ++nf) {
                const unsigned* bf = &bl[nf >> 1][(nf & 1) * 2];
                mma_f16(acc[0][nf], a0, bf);
                mma_f16(acc[1][nf], a1, bf);
            }
        }
    }

    const bool donorm = (MODE == 1) && (bxn < 2048);
    const float* sc = (bxn < 1024) ? q_scale : k_scale;
    const float fold = (bxn < 1024) ? QFOLD : 1.0f;

#pragma unroll
    for (int mf = 0; mf < 2; ++mf) {
        int r0 = bym + wm * 32 + mf * 16 + g;
#pragma unroll
        for (int nf = 0; nf < 8; ++nf) {
            int col = bxn + wn * 64 + nf * 8 + 2 * q;
            float2 bs = *(const float2*)(bias + col);
            acc[mf][nf][0] += bs.x; acc[mf][nf][1] += bs.y;
            acc[mf][nf][2] += bs.x; acc[mf][nf][3] += bs.y;
        }
        if (donorm) {
#pragma unroll
            for (int rh = 0; rh < 2; ++rh) {
                const int e0 = rh * 2, e1 = e0 + 1;
                float ss = 0.f;
#pragma unroll
                for (int nf = 0; nf < 8; ++nf)
                    ss += acc[mf][nf][e0] * acc[mf][nf][e0]
                        + acc[mf][nf][e1] * acc[mf][nf][e1];
                ss += __shfl_xor_sync(0xffffffffu, ss, 1);
                ss += __shfl_xor_sync(0xffffffffu, ss, 2);
                float rr = rsqrtf(ss * (1.0f / HD_) + EPS_) * fold;
#pragma unroll
                for (int nf = 0; nf < 8; ++nf) {
                    float2 s2 = *(const float2*)(sc + nf * 8 + 2 * q);
                    acc[mf][nf][e0] *= rr * s2.x;
                    acc[mf][nf][e1] *= rr * s2.y;
                }
            }
        }
#pragma unroll
        for (int nf = 0; nf < 8; ++nf) {
            int col = bxn + wn * 64 + nf * 8 + 2 * q;
            if (MODE == 1) {
                __half* Ch = (__half*)Cv;
                *(__half2*)(Ch + (size_t)r0 * N + col) =
                    __floats2half2_rn(acc[mf][nf][0], acc[mf][nf][1]);
                *(__half2*)(Ch + (size_t)(r0 + 8) * N + col) =
                    __floats2half2_rn(acc[mf][nf][2], acc[mf][nf][3]);
            } else {
                float* Cf = (float*)Cv;
                *(float2*)(Cf + (size_t)r0 * N + col) =
                    make_float2(acc[mf][nf][0], acc[mf][nf][1]);
                *(float2*)(Cf + (size_t)(r0 + 8) * N + col) =
                    make_float2(acc[mf][nf][2], acc[mf][nf][3]);
            }
        }
    }
}

// ---------------------------------------------------------------------------
// FP16 flash attention, FAT WARP TILE: 4 warps (128 thr), warp = 32 q x 64 keys
// (2 m-frags). Register-resident P, no online max, l via ones-column MMA.
// Same CTA footprint as before (128 q, 55KB smem, 2 CTAs/SM) but half the
// warps -> half the per-SM smem LDSM traffic at equal MMA count.
// ---------------------------------------------------------------------------
#define HTS 72
#define OFK (128 * HTS)
#define OFV (OFK + 2 * 64 * HTS)
#define KVSTG (64 * HTS * 2)
#define ATT_SMEM ((OFV + 2 * 64 * HTS) * 2)   // 55296 B

__global__ __launch_bounds__(128, 2) void attn_f16(
    const __half* __restrict__ qkv, __half* __restrict__ o)
{
    extern __shared__ __half smh[];
    __half* Qh = smh;
    __half* Kh = smh + OFK;
    __half* Vh = smh + OFV;

    const int tid = threadIdx.x;
    const int lane = tid & 31;
    const int w = tid >> 5;            // 0..3
    const int g = lane >> 2;
    const int q = lane & 3;
    const int q0 = blockIdx.x * 128;
    const int bh = blockIdx.y;
    const int b = bh >> 4;
    const int h = bh & 15;

    const __half* base = qkv + (size_t)b * S_ * 3 * D_ + h * HD_;

    // copy mapping (128 threads): chunk i => row (tid>>3)+16i, col (tid&7)*8
    const int cr = tid >> 3, cc = (tid & 7) * 8;
    const __half* ksrc = base + (size_t)cr * (3 * D_) + D_ + cc;
    const __half* vsrc = base + (size_t)cr * (3 * D_) + 2 * D_ + cc;
    const unsigned kdst = sptr(Kh) + (cr * HTS + cc) * 2;
    const unsigned vdst = sptr(Vh) + (cr * HTS + cc) * 2;

    // prologue: Q (128 rows; 8 chunks/thread) + K/V tile 0 (4+4 chunks)
#pragma unroll
    for (int i = 0; i < 8; ++i)
        cpa16(sptr(Qh) + (cr * HTS + cc) * 2 + i * (16 * HTS * 2),
              base + (size_t)(q0 + cr) * (3 * D_) + cc + (size_t)i * (16 * 3 * D_));
#pragma unroll
    for (int i = 0; i < 4; ++i) {
        cpa16(kdst + i * (16 * HTS * 2), ksrc + (size_t)i * (16 * 3 * D_));
        cpa16(vdst + i * (16 * HTS * 2), vsrc + (size_t)i * (16 * 3 * D_));
    }
    cp_commit();

    // ldsm bases: warp covers q rows [w*32, w*32+32), mf selects +0 / +16
    const unsigned qbase = sptr(Qh) + ((w * 32 + (lane & 15)) * HTS) * 2 + (lane >> 4) * 16;
    const unsigned kbase = sptr(Kh)
        + (((lane & 7) + ((lane >> 4) << 3)) * HTS) * 2 + ((lane >> 3) & 1) * 16;
    const unsigned vbase = sptr(Vh)
        + (((lane & 7) + (((lane >> 3) & 1) << 3)) * HTS) * 2 + (lane >> 4) * 16;

    const unsigned ones2[2] = {0x3C003C00u, 0x3C003C00u};   // half2(1,1)

    unsigned qfrag[2][4][4];
    float lacc[2][4] = {{0.f, 0.f, 0.f, 0.f}, {0.f, 0.f, 0.f, 0.f}};
    float acco[2][8][4];
#pragma unroll
    for (int mf = 0; mf < 2; ++mf)
#pragma unroll
        for (int nf = 0; nf < 8; ++nf)
#pragma unroll
            for (int e = 0; e < 4; ++e) acco[mf][nf][e] = 0.f;

    const int T = S_ / 64;
#pragma unroll 2
    for (int t = 0; t < T; ++t) {
        cp_wait<0>();
        __syncthreads();
        if (t + 1 < T) {
            const size_t ko = (size_t)(t + 1) * 64 * (3 * D_);
            const unsigned so = ((t + 1) & 1) * KVSTG;
#pragma unroll
            for (int i = 0; i < 4; ++i) {
                cpa16(kdst + i * (16 * HTS * 2) + so, ksrc + ko + (size_t)i * (16 * 3 * D_));
                cpa16(vdst + i * (16 * HTS * 2) + so, vsrc + ko + (size_t)i * (16 * 3 * D_));
            }
            cp_commit();
        }
        if (t == 0) {   // hoist Q fragments (constant across KV tiles)
#pragma unroll
            for (int mf = 0; mf < 2; ++mf)
#pragma unroll
                for (int ks = 0; ks < 4; ++ks)
                    ldsm4(qfrag[mf][ks][0], qfrag[mf][ks][1],
                          qfrag[mf][ks][2], qfrag[mf][ks][3],
                          qbase + mf * (16 * HTS * 2) + ks * 32);
        }

        const unsigned k_s = kbase + (t & 1) * KVSTG;
        const unsigned v_s = vbase + (t & 1) * KVSTG;

        // S = Q K^T  (K frags shared across both m-frags)
        float accs[2][8][4];
#pragma unroll
        for (int mf = 0; mf < 2; ++mf)
#pragma unroll
            for (int nf = 0; nf < 8; ++nf)
#pragma unroll
                for (int e = 0; e < 4; ++e) accs[mf][nf][e] = 0.f;
#pragma unroll
        for (int ks = 0; ks < 4; ++ks) {
            unsigned bl[4][4];
#pragma unroll
            for (int t2 = 0; t2 < 4; ++t2)
                ldsm4(bl[t2][0], bl[t2][1], bl[t2][2], bl[t2][3],
                      k_s + t2 * 16 * HTS * 2 + ks * 32);
#pragma unroll
            for (int nf = 0; nf < 8; ++nf) {
                const unsigned* bf = &bl[nf >> 1][(nf & 1) * 2];
                mma_f16(accs[0][nf], qfrag[0][ks], bf);
                mma_f16(accs[1][nf], qfrag[1][ks], bf);
            }
        }

        // p = exp2(s), packed directly as PV A-fragments (registers only)
        unsigned pa[2][4][4];
#pragma unroll
        for (int mf = 0; mf < 2; ++mf)
#pragma unroll
            for (int j = 0; j < 4; ++j) {
                pa[mf][j][0] = ex2_pack(accs[mf][2 * j][0],     accs[mf][2 * j][1]);
                pa[mf][j][1] = ex2_pack(accs[mf][2 * j][2],     accs[mf][2 * j][3]);
                pa[mf][j][2] = ex2_pack(accs[mf][2 * j + 1][0], accs[mf][2 * j + 1][1]);
                pa[mf][j][3] = ex2_pack(accs[mf][2 * j + 1][2], accs[mf][2 * j + 1][3]);
            }

        // O += P V ; l += P * ones  (V frags shared across both m-frags)
#pragma unroll
        for (int ks = 0; ks < 4; ++ks) {
            unsigned bl[4][4];
#pragma unroll
            for (int t2 = 0; t2 < 4; ++t2)
                ldsm4t(bl[t2][0], bl[t2][1], bl[t2][2], bl[t2][3],
                       v_s + ks * 16 * HTS * 2 + t2 * 32);
#pragma unroll
            for (int nf = 0; nf < 8; ++nf) {
                const unsigned* bf = &bl[nf >> 1][(nf & 1) * 2];
                mma_f16(acco[0][nf], pa[0][ks], bf);
                mma_f16(acco[1][nf], pa[1][ks], bf);
            }
            mma_f16(lacc[0], pa[0][ks], ones2);
            mma_f16(lacc[1], pa[1][ks], ones2);
        }
    }

    // epilogue: O / l, store fp16
#pragma unroll
    for (int mf = 0; mf < 2; ++mf)
#pragma unroll
    for (int rh = 0; rh < 2; ++rh) {
        float inv = 1.0f / lacc[mf][rh * 2];
        int row = q0 + w * 32 + mf * 16 + g + rh * 8;
        __half* orow = o + (size_t)(b * S_ + row) * D_ + h * HD_;
        const int e0 = rh * 2, e1 = e0 + 1;
#pragma unroll
        for (int nf = 0; nf < 8; ++nf)
            *(__half2*)(orow + nf * 8 + 2 * q) =
                __floats2half2_rn(acco[mf][nf][e0] * inv, acco[mf][nf][e1] * inv);
    }
}

// ---------------------------------------------------------------------------
extern "C" void kernel_launch(void* const* d_in, const int* in_sizes, int n_in,
                              void* d_out, int out_size)
{
    const float* x       = (const float*)d_in[0];
    const float* Wqkv    = (const float*)d_in[1];
    const float* bqkv    = (const float*)d_in[2];
    const float* Wout    = (const float*)d_in[3];
    const float* bout    = (const float*)d_in[4];
    const float* q_scale = (const float*)d_in[5];
    const float* k_scale = (const float*)d_in[6];
    float* out = (float*)d_out;

    __half* qkvh; cudaGetSymbolAddress((void**)&qkvh, g_qkvh);
    __half* oh;   cudaGetSymbolAddress((void**)&oh,   g_oh);
    __half* xh;   cudaGetSymbolAddress((void**)&xh,   g_xh);
    __half* wqh;  cudaGetSymbolAddress((void**)&wqh,  g_wqh);
    __half* woh;  cudaGetSymbolAddress((void**)&woh,  g_woh);

    cudaFuncSetAttribute((const void*)gemm_f16<3 * D_, D_, 1>,
                         cudaFuncAttributeMaxDynamicSharedMemorySize, GEMM_SMEM);
    cudaFuncSetAttribute((const void*)gemm_f16<D_, D_, 0>,
                         cudaFuncAttributeMaxDynamicSharedMemorySize, GEMM_SMEM);
    cudaFuncSetAttribute((const void*)attn_f16,
                         cudaFuncAttributeMaxDynamicSharedMemorySize, ATT_SMEM);

    // 0) pre-convert x + weights to fp16 (weights transposed)
    cvt_h<<<(B_ * S_ * D_ / 4 + 255) / 256, 256>>>(x, xh, B_ * S_ * D_ / 4);
    tcvt_h<<<dim3(3 * D_ / 32, D_ / 32), 256>>>(Wqkv, wqh, D_, 3 * D_);
    tcvt_h<<<dim3(D_ / 32, D_ / 32), 256>>>(Wout, woh, D_, D_);

    // 1) QKV projection + fused RMSNorm, fp16 output
    gemm_f16<3 * D_, D_, 1><<<dim3(3 * D_ / 128, (B_ * S_) / 128), 256, GEMM_SMEM>>>(
        xh, wqh, bqkv, (void*)qkvh, q_scale, k_scale);

    // 2) attention (fat warp tile, register-resident P), fp16 output
    attn_f16<<<dim3(S_ / 128, B_ * H_), 128, ATT_SMEM>>>(qkvh, oh);

    // 3) output projection (fp32 output)
    gemm_f16<D_, D_, 0><<<dim3(D_ / 128, (B_ * S_) / 128), 256, GEMM_SMEM>>>(
        oh, woh, bout, (void*)out, q_scale, k_scale);
}